// round 3
// baseline (speedup 1.0000x reference)
#include <cuda_runtime.h>
#include <math.h>

#define DEVINL __device__ __forceinline__

namespace {

constexpr int Bn   = 32;   // batch
constexpr int Tn   = 256;  // timesteps
constexpr int Nn   = 128;  // nodes
constexpr int DINn = 16;   // input features
constexpr int Un   = 64;   // hidden units
constexpr int Cn   = 4;    // classes
constexpr int CB   = 16;   // channel block
constexpr int NTHREADS = 512;
constexpr int PST = 129;   // padded support row stride (bank-conflict free)

struct Smem {
  float P[Nn * PST];      // support, padded rows
  float h0[Nn * Un];      // layer-0 hidden
  float h1[Nn * Un];      // layer-1 hidden
  float xbuf[Nn * DINn];  // current input frame
  float zb0[Nn * CB];     // diffusion block buffers
  float zb1[Nn * CB];
  float zb2[Nn * CB];
  float ubuf[Nn * Un];    // update gate
  float rh[Nn * Un];      // reset gate * h
};

// zb1[n][c] = sum_k P[n][k] * zb0[k][c]   (per thread: 1 node x 4 channels)
DEVINL void diffuse1(Smem& S, int tid) {
  const int c4 = (tid & 3) * 4;
  const int n  = tid >> 2;
  const float* Pr = &S.P[n * PST];
  float a0 = 0.f, a1 = 0.f, a2 = 0.f, a3 = 0.f;
#pragma unroll 8
  for (int k = 0; k < Nn; ++k) {
    const float p = Pr[k];
    const float4 z = *reinterpret_cast<const float4*>(&S.zb0[k * CB + c4]);
    a0 = fmaf(p, z.x, a0); a1 = fmaf(p, z.y, a1);
    a2 = fmaf(p, z.z, a2); a3 = fmaf(p, z.w, a3);
  }
  *reinterpret_cast<float4*>(&S.zb1[n * CB + c4]) = make_float4(a0, a1, a2, a3);
}

// zb2 = 2 * P * zb1 - zb0
DEVINL void diffuse2(Smem& S, int tid) {
  const int c4 = (tid & 3) * 4;
  const int n  = tid >> 2;
  const float* Pr = &S.P[n * PST];
  float a0 = 0.f, a1 = 0.f, a2 = 0.f, a3 = 0.f;
#pragma unroll 8
  for (int k = 0; k < Nn; ++k) {
    const float p = Pr[k];
    const float4 z = *reinterpret_cast<const float4*>(&S.zb1[k * CB + c4]);
    a0 = fmaf(p, z.x, a0); a1 = fmaf(p, z.y, a1);
    a2 = fmaf(p, z.z, a2); a3 = fmaf(p, z.w, a3);
  }
  const float4 z0 = *reinterpret_cast<const float4*>(&S.zb0[n * CB + c4]);
  *reinterpret_cast<float4*>(&S.zb2[n * CB + c4]) =
      make_float4(2.f * a0 - z0.x, 2.f * a1 - z0.y,
                  2.f * a2 - z0.z, 2.f * a3 - z0.w);
}

// Accumulate one channel block of the projection:
// acc[n][o] += sum_{cc,m} z_m[n][cb+cc] * W[(cb+cc)*3+m][o]
template <int OB>
DEVINL void accum_block(Smem& S, int tid, const float* __restrict__ W, int cb,
                        float acc[4][OB]) {
  constexpr int COUT = OB * 16;
  const int og = tid & 15;
  const int rg = tid >> 4;
#pragma unroll 2
  for (int cc = 0; cc < CB; ++cc) {
    const int c = cb + cc;
    const float* w0 = W + (size_t)(c * 3) * COUT + og * OB;
    float z0[4], z1[4], z2[4];
#pragma unroll
    for (int i = 0; i < 4; ++i) {
      const int n = rg * 4 + i;
      z0[i] = S.zb0[n * CB + cc];
      z1[i] = S.zb1[n * CB + cc];
      z2[i] = S.zb2[n * CB + cc];
    }
#pragma unroll
    for (int j = 0; j < OB; ++j) {
      const float wa = w0[j];
      const float wb = w0[COUT + j];
      const float wc = w0[2 * COUT + j];
#pragma unroll
      for (int i = 0; i < 4; ++i)
        acc[i][j] = fmaf(z0[i], wa, fmaf(z1[i], wb, fmaf(z2[i], wc, acc[i][j])));
    }
  }
}

// Full graph-conv + projection: y = [z, Pz, 2P^2 z - z] @ W  (bias added in epilogue)
// z = concat(x-part (XCH ch), h-part (64 ch)); all sources live in SMEM.
template <int XCH, int OB>
DEVINL void gconv(Smem& S, int tid, const float* xs, int xstride,
                  const float* hs, const float* __restrict__ W, float acc[4][OB]) {
  constexpr int CIN = XCH + Un;
  const int ns = tid >> 2;
  const int c4 = (tid & 3) * 4;
  for (int cb = 0; cb < CIN; cb += CB) {
    const float* src;
    int stride, col0;
    if (cb < XCH) { src = xs; stride = xstride; col0 = cb; }
    else          { src = hs; stride = Un;      col0 = cb - XCH; }
    const float4 v =
        *reinterpret_cast<const float4*>(src + ns * stride + col0 + c4);
    *reinterpret_cast<float4*>(&S.zb0[ns * CB + c4]) = v;
    __syncthreads();
    diffuse1(S, tid);
    __syncthreads();
    diffuse2(S, tid);
    __syncthreads();
    accum_block<OB>(S, tid, W, cb, acc);
    __syncthreads();
  }
}

// One DCGRU cell: h <- u*h + (1-u)*tanh(gconv([x, r*h]) Wc + bc),
//   [r|u] = sigmoid(gconv([x, h]) Wg + bg)
template <int XCH>
DEVINL void cell(Smem& S, int tid, const float* xs, int xstride, float* h,
                 const float* __restrict__ Wg, const float* __restrict__ bg,
                 const float* __restrict__ Wc, const float* __restrict__ bc) {
  const int og = tid & 15;
  const int rg = tid >> 4;
  // ---- gate ----
  {
    float acc[4][8];
#pragma unroll
    for (int i = 0; i < 4; ++i)
#pragma unroll
      for (int j = 0; j < 8; ++j) acc[i][j] = 0.f;
    gconv<XCH, 8>(S, tid, xs, xstride, h, Wg, acc);
#pragma unroll
    for (int j = 0; j < 8; ++j) {
      const int o = og * 8 + j;
      const float bias = bg[o];
#pragma unroll
      for (int i = 0; i < 4; ++i) {
        const int n = rg * 4 + i;
        const float v = 1.f / (1.f + __expf(-(acc[i][j] + bias)));
        if (o < Un) S.rh[n * Un + o] = v * h[n * Un + o];       // r * h
        else        S.ubuf[n * Un + (o - Un)] = v;              // u
      }
    }
    __syncthreads();
  }
  // ---- candidate + state update ----
  {
    float acc[4][4];
#pragma unroll
    for (int i = 0; i < 4; ++i)
#pragma unroll
      for (int j = 0; j < 4; ++j) acc[i][j] = 0.f;
    gconv<XCH, 4>(S, tid, xs, xstride, S.rh, Wc, acc);
#pragma unroll
    for (int j = 0; j < 4; ++j) {
      const int o = og * 4 + j;
      const float bias = bc[o];
#pragma unroll
      for (int i = 0; i < 4; ++i) {
        const int n = rg * 4 + i;
        const float cv = tanhf(acc[i][j] + bias);
        const float u = S.ubuf[n * Un + o];
        h[n * Un + o] = u * h[n * Un + o] + (1.f - u) * cv;
      }
    }
    __syncthreads();
  }
}

}  // namespace

__global__ void __launch_bounds__(NTHREADS, 1) dcgru_kernel(
    const float* __restrict__ x_all,   // (B,T,N,DIN)
    const int* __restrict__ seq_len,   // (B)
    const float* __restrict__ support, // (N,N)
    const float* __restrict__ W0g, const float* __restrict__ b0g,
    const float* __restrict__ W0c, const float* __restrict__ b0c,
    const float* __restrict__ W1g, const float* __restrict__ b1g,
    const float* __restrict__ W1c, const float* __restrict__ b1c,
    const float* __restrict__ Wfc, const float* __restrict__ bfc,
    float* __restrict__ out) {        // (B,C)
  extern __shared__ float smraw[];
  Smem& S = *reinterpret_cast<Smem*>(smraw);
  const int b = blockIdx.x;
  const int tid = threadIdx.x;

  // Load support into padded SMEM; zero hidden states.
  for (int i = tid; i < Nn * Nn; i += NTHREADS)
    S.P[(i >> 7) * PST + (i & 127)] = support[i];
  for (int i = tid; i < Nn * Un; i += NTHREADS) {
    S.h0[i] = 0.f;
    S.h1[i] = 0.f;
  }
  __syncthreads();

  const int tlast = seq_len[b] - 1;  // only steps <= tlast affect the output

  for (int t = 0; t <= tlast; ++t) {
    // stage current input frame (2048 floats = 512 float4)
    const float4* xt = reinterpret_cast<const float4*>(
        x_all + ((size_t)b * Tn + t) * (Nn * DINn));
    reinterpret_cast<float4*>(S.xbuf)[tid] = xt[tid];
    __syncthreads();
    cell<DINn>(S, tid, S.xbuf, DINn, S.h0, W0g, b0g, W0c, b0c);
    cell<Un>(S, tid, S.h0, Un, S.h1, W1g, b1g, W1c, b1c);
  }

  // Classifier on h1 at t = tlast: max_n( relu(h1) @ Wfc + bfc )
  {
    const int n = tid >> 2;
    const int c = tid & 3;
    float a = 0.f;
#pragma unroll 8
    for (int u = 0; u < Un; ++u)
      a = fmaf(fmaxf(S.h1[n * Un + u], 0.f), Wfc[u * Cn + c], a);
    S.zb0[n * Cn + c] = a + bfc[c];
    __syncthreads();
    if (tid < Cn) {
      float m = S.zb0[tid];
      for (int n2 = 1; n2 < Nn; ++n2) m = fmaxf(m, S.zb0[n2 * Cn + tid]);
      out[b * Cn + tid] = m;
    }
  }
}

extern "C" void kernel_launch(void* const* d_in, const int* in_sizes, int n_in,
                              void* d_out, int out_size) {
  const float* x   = (const float*)d_in[0];
  const int*   sl  = (const int*)d_in[1];
  const float* sup = (const float*)d_in[2];
  const float* W0g = (const float*)d_in[3];
  const float* b0g = (const float*)d_in[4];
  const float* W0c = (const float*)d_in[5];
  const float* b0c = (const float*)d_in[6];
  const float* W1g = (const float*)d_in[7];
  const float* b1g = (const float*)d_in[8];
  const float* W1c = (const float*)d_in[9];
  const float* b1c = (const float*)d_in[10];
  const float* Wfc = (const float*)d_in[11];
  const float* bfc = (const float*)d_in[12];
  float* out = (float*)d_out;

  const size_t smem = sizeof(Smem);
  cudaFuncSetAttribute(dcgru_kernel,
                       cudaFuncAttributeMaxDynamicSharedMemorySize, (int)smem);
  dcgru_kernel<<<Bn, NTHREADS, smem>>>(x, sl, sup, W0g, b0g, W0c, b0c,
                                       W1g, b1g, W1c, b1c, Wfc, bfc, out);
}

// round 5
// speedup vs baseline: 1.0009x; 1.0009x over previous
#include <cuda_runtime.h>
#include <math.h>

#define DEVINL __device__ __forceinline__

namespace {

constexpr int Bn   = 32;   // batch
constexpr int Tn   = 256;  // timesteps
constexpr int Nn   = 128;  // nodes
constexpr int DINn = 16;   // input features
constexpr int Un   = 64;   // hidden units
constexpr int Cn   = 4;    // classes
constexpr int CB   = 16;   // channel block
constexpr int NTHREADS = 512;
constexpr int PST = 129;   // padded support row stride (bank-conflict free)

struct Smem {
  float P[Nn * PST];      // support, padded rows
  float h0[Nn * Un];      // layer-0 hidden
  float h1[Nn * Un];      // layer-1 hidden
  float xbuf[Nn * DINn];  // current input frame
  float zb0[Nn * CB];     // diffusion block buffers
  float zb1[Nn * CB];
  float zb2[Nn * CB];
  float ubuf[Nn * Un];    // update gate
  float rh[Nn * Un];      // reset gate * h
};

// zb1[n][c] = sum_k P[n][k] * zb0[k][c]   (per thread: 1 node x 4 channels)
DEVINL void diffuse1(Smem& S, int tid) {
  const int c4 = (tid & 3) * 4;
  const int n  = tid >> 2;
  const float* Pr = &S.P[n * PST];
  float a0 = 0.f, a1 = 0.f, a2 = 0.f, a3 = 0.f;
#pragma unroll 8
  for (int k = 0; k < Nn; ++k) {
    const float p = Pr[k];
    const float4 z = *reinterpret_cast<const float4*>(&S.zb0[k * CB + c4]);
    a0 = fmaf(p, z.x, a0); a1 = fmaf(p, z.y, a1);
    a2 = fmaf(p, z.z, a2); a3 = fmaf(p, z.w, a3);
  }
  *reinterpret_cast<float4*>(&S.zb1[n * CB + c4]) = make_float4(a0, a1, a2, a3);
}

// zb2 = 2 * P * zb1 - zb0
DEVINL void diffuse2(Smem& S, int tid) {
  const int c4 = (tid & 3) * 4;
  const int n  = tid >> 2;
  const float* Pr = &S.P[n * PST];
  float a0 = 0.f, a1 = 0.f, a2 = 0.f, a3 = 0.f;
#pragma unroll 8
  for (int k = 0; k < Nn; ++k) {
    const float p = Pr[k];
    const float4 z = *reinterpret_cast<const float4*>(&S.zb1[k * CB + c4]);
    a0 = fmaf(p, z.x, a0); a1 = fmaf(p, z.y, a1);
    a2 = fmaf(p, z.z, a2); a3 = fmaf(p, z.w, a3);
  }
  const float4 z0 = *reinterpret_cast<const float4*>(&S.zb0[n * CB + c4]);
  *reinterpret_cast<float4*>(&S.zb2[n * CB + c4]) =
      make_float4(2.f * a0 - z0.x, 2.f * a1 - z0.y,
                  2.f * a2 - z0.z, 2.f * a3 - z0.w);
}

// Accumulate one channel block of the projection:
// acc[n][o] += sum_{cc,m} z_m[n][cb+cc] * W[(cb+cc)*3+m][o]
template <int OB>
DEVINL void accum_block(Smem& S, int tid, const float* __restrict__ W, int cb,
                        float acc[4][OB]) {
  constexpr int COUT = OB * 16;
  const int og = tid & 15;
  const int rg = tid >> 4;
#pragma unroll 2
  for (int cc = 0; cc < CB; ++cc) {
    const int c = cb + cc;
    const float* w0 = W + (size_t)(c * 3) * COUT + og * OB;
    float z0[4], z1[4], z2[4];
#pragma unroll
    for (int i = 0; i < 4; ++i) {
      const int n = rg * 4 + i;
      z0[i] = S.zb0[n * CB + cc];
      z1[i] = S.zb1[n * CB + cc];
      z2[i] = S.zb2[n * CB + cc];
    }
#pragma unroll
    for (int j = 0; j < OB; ++j) {
      const float wa = w0[j];
      const float wb = w0[COUT + j];
      const float wc = w0[2 * COUT + j];
#pragma unroll
      for (int i = 0; i < 4; ++i)
        acc[i][j] = fmaf(z0[i], wa, fmaf(z1[i], wb, fmaf(z2[i], wc, acc[i][j])));
    }
  }
}

// Full graph-conv + projection: y = [z, Pz, 2P^2 z - z] @ W  (bias added in epilogue)
// z = concat(x-part (XCH ch), h-part (64 ch)); all sources live in SMEM.
template <int XCH, int OB>
DEVINL void gconv(Smem& S, int tid, const float* xs, int xstride,
                  const float* hs, const float* __restrict__ W, float acc[4][OB]) {
  constexpr int CIN = XCH + Un;
  const int ns = tid >> 2;
  const int c4 = (tid & 3) * 4;
  for (int cb = 0; cb < CIN; cb += CB) {
    const float* src;
    int stride, col0;
    if (cb < XCH) { src = xs; stride = xstride; col0 = cb; }
    else          { src = hs; stride = Un;      col0 = cb - XCH; }
    const float4 v =
        *reinterpret_cast<const float4*>(src + ns * stride + col0 + c4);
    *reinterpret_cast<float4*>(&S.zb0[ns * CB + c4]) = v;
    __syncthreads();
    diffuse1(S, tid);
    __syncthreads();
    diffuse2(S, tid);
    __syncthreads();
    accum_block<OB>(S, tid, W, cb, acc);
    __syncthreads();
  }
}

// One DCGRU cell: h <- u*h + (1-u)*tanh(gconv([x, r*h]) Wc + bc),
//   [r|u] = sigmoid(gconv([x, h]) Wg + bg)
template <int XCH>
DEVINL void cell(Smem& S, int tid, const float* xs, int xstride, float* h,
                 const float* __restrict__ Wg, const float* __restrict__ bg,
                 const float* __restrict__ Wc, const float* __restrict__ bc) {
  const int og = tid & 15;
  const int rg = tid >> 4;
  // ---- gate ----
  {
    float acc[4][8];
#pragma unroll
    for (int i = 0; i < 4; ++i)
#pragma unroll
      for (int j = 0; j < 8; ++j) acc[i][j] = 0.f;
    gconv<XCH, 8>(S, tid, xs, xstride, h, Wg, acc);
#pragma unroll
    for (int j = 0; j < 8; ++j) {
      const int o = og * 8 + j;
      const float bias = bg[o];
#pragma unroll
      for (int i = 0; i < 4; ++i) {
        const int n = rg * 4 + i;
        const float v = 1.f / (1.f + __expf(-(acc[i][j] + bias)));
        if (o < Un) S.rh[n * Un + o] = v * h[n * Un + o];       // r * h
        else        S.ubuf[n * Un + (o - Un)] = v;              // u
      }
    }
    __syncthreads();
  }
  // ---- candidate + state update ----
  {
    float acc[4][4];
#pragma unroll
    for (int i = 0; i < 4; ++i)
#pragma unroll
      for (int j = 0; j < 4; ++j) acc[i][j] = 0.f;
    gconv<XCH, 4>(S, tid, xs, xstride, S.rh, Wc, acc);
#pragma unroll
    for (int j = 0; j < 4; ++j) {
      const int o = og * 4 + j;
      const float bias = bc[o];
#pragma unroll
      for (int i = 0; i < 4; ++i) {
        const int n = rg * 4 + i;
        const float cv = tanhf(acc[i][j] + bias);
        const float u = S.ubuf[n * Un + o];
        h[n * Un + o] = u * h[n * Un + o] + (1.f - u) * cv;
      }
    }
    __syncthreads();
  }
}

}  // namespace

__global__ void __launch_bounds__(NTHREADS, 1) dcgru_kernel(
    const float* __restrict__ x_all,   // (B,T,N,DIN)
    const int* __restrict__ seq_len,   // (B)
    const float* __restrict__ support, // (N,N)
    const float* __restrict__ W0g, const float* __restrict__ b0g,
    const float* __restrict__ W0c, const float* __restrict__ b0c,
    const float* __restrict__ W1g, const float* __restrict__ b1g,
    const float* __restrict__ W1c, const float* __restrict__ b1c,
    const float* __restrict__ Wfc, const float* __restrict__ bfc,
    float* __restrict__ out) {        // (B,C)
  extern __shared__ float smraw[];
  Smem& S = *reinterpret_cast<Smem*>(smraw);
  const int b = blockIdx.x;
  const int tid = threadIdx.x;

  // Load support into padded SMEM; zero hidden states.
  for (int i = tid; i < Nn * Nn; i += NTHREADS)
    S.P[(i >> 7) * PST + (i & 127)] = support[i];
  for (int i = tid; i < Nn * Un; i += NTHREADS) {
    S.h0[i] = 0.f;
    S.h1[i] = 0.f;
  }
  __syncthreads();

  const int tlast = seq_len[b] - 1;  // only steps <= tlast affect the output

  for (int t = 0; t <= tlast; ++t) {
    // stage current input frame (2048 floats = 512 float4)
    const float4* xt = reinterpret_cast<const float4*>(
        x_all + ((size_t)b * Tn + t) * (Nn * DINn));
    reinterpret_cast<float4*>(S.xbuf)[tid] = xt[tid];
    __syncthreads();
    cell<DINn>(S, tid, S.xbuf, DINn, S.h0, W0g, b0g, W0c, b0c);
    cell<Un>(S, tid, S.h0, Un, S.h1, W1g, b1g, W1c, b1c);
  }

  // Classifier on h1 at t = tlast: max_n( relu(h1) @ Wfc + bfc )
  {
    const int n = tid >> 2;
    const int c = tid & 3;
    float a = 0.f;
#pragma unroll 8
    for (int u = 0; u < Un; ++u)
      a = fmaf(fmaxf(S.h1[n * Un + u], 0.f), Wfc[u * Cn + c], a);
    S.zb0[n * Cn + c] = a + bfc[c];
    __syncthreads();
    if (tid < Cn) {
      float m = S.zb0[tid];
      for (int n2 = 1; n2 < Nn; ++n2) m = fmaxf(m, S.zb0[n2 * Cn + tid]);
      out[b * Cn + tid] = m;
    }
  }
}

extern "C" void kernel_launch(void* const* d_in, const int* in_sizes, int n_in,
                              void* d_out, int out_size) {
  const float* x   = (const float*)d_in[0];
  const int*   sl  = (const int*)d_in[1];
  const float* sup = (const float*)d_in[2];
  const float* W0g = (const float*)d_in[3];
  const float* b0g = (const float*)d_in[4];
  const float* W0c = (const float*)d_in[5];
  const float* b0c = (const float*)d_in[6];
  const float* W1g = (const float*)d_in[7];
  const float* b1g = (const float*)d_in[8];
  const float* W1c = (const float*)d_in[9];
  const float* b1c = (const float*)d_in[10];
  const float* Wfc = (const float*)d_in[11];
  const float* bfc = (const float*)d_in[12];
  float* out = (float*)d_out;

  const size_t smem = sizeof(Smem);
  cudaFuncSetAttribute(dcgru_kernel,
                       cudaFuncAttributeMaxDynamicSharedMemorySize, (int)smem);
  dcgru_kernel<<<Bn, NTHREADS, smem>>>(x, sl, sup, W0g, b0g, W0c, b0c,
                                       W1g, b1g, W1c, b1c, Wfc, bfc, out);
}

// round 7
// speedup vs baseline: 2.7112x; 2.7086x over previous
#include <cuda_runtime.h>
#include <cooperative_groups.h>
#include <math.h>

namespace cgx = cooperative_groups;
#define DEVINL __device__ __forceinline__

namespace {

constexpr int Bn   = 32;   // batch
constexpr int Tn   = 256;  // timesteps
constexpr int Nn   = 128;  // nodes
constexpr int DINn = 16;   // input features
constexpr int Un   = 64;   // hidden units
constexpr int Cn   = 4;    // classes
constexpr int CLS  = 4;    // cluster size (CTAs per batch)
constexpr int NP   = 32;   // nodes owned per CTA
constexpr int NT   = 512;  // threads per CTA
constexpr int PST  = 129;  // padded P row stride

struct Smem {
  float P[NP * PST];    // own 32 rows of support (padded)
  float h0[Nn * Un];    // replicated full hidden, layer 0
  float h1[Nn * Un];    // replicated full hidden, layer 1
  float xb[Nn * DINn];  // current input frame (replicated)
  float rh[Nn * Un];    // replicated r*h
  float z1[Nn * Nn];    // full P@z (stride = CIN), assembled via DSMEM
  float z2[NP * Nn];    // own rows of 2P@z1 - z  (stride = CIN)
  float ub[NP * Un];    // own update gate
};

// ---- diffusion hop 1: z1[n][:] = sum_k P[n][k] z0[k][:], n = own nodes.
// Each thread: 1 node x up to 8 channels (2 float4). Result scattered to all
// 4 ranks' z1 buffers so everyone can run hop 2.
template <int CH0>
DEVINL void diffuse1(Smem& S, Smem* const* Sp, int tid, int ng_base,
                     const float* __restrict__ s0, const float* __restrict__ s1) {
  constexpr int CIN = CH0 + Un;
  constexpr int NJ = (CIN + 63) / 64;
  const int n = tid >> 4;
  const int cg = tid & 15;
  const float* Pr = &S.P[n * PST];
  float4 a[NJ];
#pragma unroll
  for (int j = 0; j < NJ; ++j) a[j] = make_float4(0.f, 0.f, 0.f, 0.f);
#pragma unroll 8
  for (int k = 0; k < Nn; ++k) {
    const float p = Pr[k];
#pragma unroll
    for (int j = 0; j < NJ; ++j) {
      const int c4 = (cg + 16 * j) * 4;
      if (c4 < CIN) {
        const float* src = (c4 < CH0) ? (s0 + k * CH0 + c4)
                                      : (s1 + k * Un + (c4 - CH0));
        const float4 z = *reinterpret_cast<const float4*>(src);
        a[j].x = fmaf(p, z.x, a[j].x);
        a[j].y = fmaf(p, z.y, a[j].y);
        a[j].z = fmaf(p, z.z, a[j].z);
        a[j].w = fmaf(p, z.w, a[j].w);
      }
    }
  }
  const int ng = ng_base + n;
#pragma unroll
  for (int j = 0; j < NJ; ++j) {
    const int c4 = (cg + 16 * j) * 4;
    if (c4 < CIN) {
#pragma unroll
      for (int r = 0; r < CLS; ++r)
        *reinterpret_cast<float4*>(&Sp[r]->z1[ng * CIN + c4]) = a[j];
    }
  }
}

// ---- diffusion hop 2: z2[n][:] = 2 * sum_k P[n][k] z1[k][:] - z0[n][:] (own n, local)
template <int CH0>
DEVINL void diffuse2(Smem& S, int tid, int ng_base,
                     const float* __restrict__ s0, const float* __restrict__ s1) {
  constexpr int CIN = CH0 + Un;
  constexpr int NJ = (CIN + 63) / 64;
  const int n = tid >> 4;
  const int cg = tid & 15;
  const int ng = ng_base + n;
  const float* Pr = &S.P[n * PST];
  float4 a[NJ];
#pragma unroll
  for (int j = 0; j < NJ; ++j) a[j] = make_float4(0.f, 0.f, 0.f, 0.f);
#pragma unroll 8
  for (int k = 0; k < Nn; ++k) {
    const float p = Pr[k];
#pragma unroll
    for (int j = 0; j < NJ; ++j) {
      const int c4 = (cg + 16 * j) * 4;
      if (c4 < CIN) {
        const float4 z = *reinterpret_cast<const float4*>(&S.z1[k * CIN + c4]);
        a[j].x = fmaf(p, z.x, a[j].x);
        a[j].y = fmaf(p, z.y, a[j].y);
        a[j].z = fmaf(p, z.z, a[j].z);
        a[j].w = fmaf(p, z.w, a[j].w);
      }
    }
  }
#pragma unroll
  for (int j = 0; j < NJ; ++j) {
    const int c4 = (cg + 16 * j) * 4;
    if (c4 < CIN) {
      const float* src = (c4 < CH0) ? (s0 + ng * CH0 + c4)
                                    : (s1 + ng * Un + (c4 - CH0));
      const float4 z0 = *reinterpret_cast<const float4*>(src);
      *reinterpret_cast<float4*>(&S.z2[n * CIN + c4]) =
          make_float4(2.f * a[j].x - z0.x, 2.f * a[j].y - z0.y,
                      2.f * a[j].z - z0.z, 2.f * a[j].w - z0.w);
    }
  }
}

// ---- projection: acc[o] = sum_{c,m} z_m[n][c] * W[c*3+m][o], own n, o = og*OB..+OB-1
template <int CH0, int OB>
DEVINL void accum(Smem& S, int tid, int ng_base, const float* __restrict__ W,
                  const float* __restrict__ s0, const float* __restrict__ s1,
                  float acc[OB]) {
  constexpr int CIN = CH0 + Un;
  constexpr int COUT = OB * 16;
  const int n = tid >> 4;
  const int og = tid & 15;
  const int ng = ng_base + n;
  const float* z1r = &S.z1[ng * CIN];
  const float* z2r = &S.z2[n * CIN];
#pragma unroll 2
  for (int c = 0; c < CIN; ++c) {
    const float z0 = (c < CH0) ? s0[ng * CH0 + c] : s1[ng * Un + (c - CH0)];
    const float z1v = z1r[c];
    const float z2v = z2r[c];
    const float* wb = W + (size_t)(c * 3) * COUT + og * OB;
#pragma unroll
    for (int q = 0; q < OB / 4; ++q) {
      const float4 w0 = *reinterpret_cast<const float4*>(wb + q * 4);
      const float4 w1 = *reinterpret_cast<const float4*>(wb + COUT + q * 4);
      const float4 w2 = *reinterpret_cast<const float4*>(wb + 2 * COUT + q * 4);
      acc[q * 4 + 0] = fmaf(z0, w0.x, fmaf(z1v, w1.x, fmaf(z2v, w2.x, acc[q * 4 + 0])));
      acc[q * 4 + 1] = fmaf(z0, w0.y, fmaf(z1v, w1.y, fmaf(z2v, w2.y, acc[q * 4 + 1])));
      acc[q * 4 + 2] = fmaf(z0, w0.z, fmaf(z1v, w1.z, fmaf(z2v, w2.z, acc[q * 4 + 2])));
      acc[q * 4 + 3] = fmaf(z0, w0.w, fmaf(z1v, w1.w, fmaf(z2v, w2.w, acc[q * 4 + 3])));
    }
  }
}

// ---- one DCGRU cell, cluster-cooperative. h is the local replicated hidden
// buffer (S.h0 or S.h1); updates are scattered to all ranks.
template <int CH0>
DEVINL void cell(cgx::cluster_group& cl, Smem& S, Smem* const* Sp, int tid,
                 int rank, const float* __restrict__ s0, float* __restrict__ h,
                 const float* __restrict__ Wg, const float* __restrict__ bg,
                 const float* __restrict__ Wc, const float* __restrict__ bc) {
  const int ng_base = rank * NP;
  const int n = tid >> 4;
  const int og = tid & 15;
  const int ng = ng_base + n;
  const size_t hoff = (size_t)((const char*)h - (const char*)&S);

  // ================= gate =================
  cl.sync();  // inputs (h / prev-phase scatters) visible everywhere; z1 free
  diffuse1<CH0>(S, Sp, tid, ng_base, s0, h);
  cl.sync();  // z1 fully assembled in every rank
  diffuse2<CH0>(S, tid, ng_base, s0, h);
  __syncthreads();
  {
    float acc[8];
#pragma unroll
    for (int j = 0; j < 8; ++j) acc[j] = 0.f;
    accum<CH0, 8>(S, tid, ng_base, Wg, s0, h, acc);
    float v[8];
#pragma unroll
    for (int j = 0; j < 8; ++j) {
      const int o = og * 8 + j;
      v[j] = 1.f / (1.f + __expf(-(acc[j] + bg[o])));
    }
    if (og < 8) {  // r-part: o in [0,64) -> rh, scattered to all ranks
      const float* hr = &h[ng * Un + og * 8];
      const float4 r0 = make_float4(v[0] * hr[0], v[1] * hr[1],
                                    v[2] * hr[2], v[3] * hr[3]);
      const float4 r1 = make_float4(v[4] * hr[4], v[5] * hr[5],
                                    v[6] * hr[6], v[7] * hr[7]);
#pragma unroll
      for (int r = 0; r < CLS; ++r) {
        float4* d = reinterpret_cast<float4*>(&Sp[r]->rh[ng * Un + og * 8]);
        d[0] = r0;
        d[1] = r1;
      }
    } else {  // u-part: o in [64,128) -> local ub
      float4* d = reinterpret_cast<float4*>(&S.ub[n * Un + (og - 8) * 8]);
      d[0] = make_float4(v[0], v[1], v[2], v[3]);
      d[1] = make_float4(v[4], v[5], v[6], v[7]);
    }
  }

  // ================= candidate + update =================
  cl.sync();  // rh gathered everywhere; all ranks past gate accum (z1 free)
  diffuse1<CH0>(S, Sp, tid, ng_base, s0, S.rh);
  cl.sync();
  diffuse2<CH0>(S, tid, ng_base, s0, S.rh);
  __syncthreads();
  {
    float acc[4] = {0.f, 0.f, 0.f, 0.f};
    accum<CH0, 4>(S, tid, ng_base, Wc, s0, S.rh, acc);
    const int o0 = og * 4;
    const float* hr = &h[ng * Un + o0];
    const float* ur = &S.ub[n * Un + o0];
    float v[4];
#pragma unroll
    for (int j = 0; j < 4; ++j) {
      const float cv = tanhf(acc[j] + bc[o0 + j]);
      const float u = ur[j];
      v[j] = u * hr[j] + (1.f - u) * cv;
    }
    const float4 hv = make_float4(v[0], v[1], v[2], v[3]);
#pragma unroll
    for (int r = 0; r < CLS; ++r) {
      float* hp = reinterpret_cast<float*>((char*)Sp[r] + hoff);
      *reinterpret_cast<float4*>(&hp[ng * Un + o0]) = hv;
    }
  }
}

}  // namespace

__global__ void __launch_bounds__(NT, 1) __cluster_dims__(CLS, 1, 1)
dcgru_kernel(
    const float* __restrict__ x_all,   // (B,T,N,DIN)
    const int* __restrict__ seq_len,   // (B)
    const float* __restrict__ support, // (N,N)
    const float* __restrict__ W0g, const float* __restrict__ b0g,
    const float* __restrict__ W0c, const float* __restrict__ b0c,
    const float* __restrict__ W1g, const float* __restrict__ b1g,
    const float* __restrict__ W1c, const float* __restrict__ b1c,
    const float* __restrict__ Wfc, const float* __restrict__ bfc,
    float* __restrict__ out) {         // (B,C)
  extern __shared__ float smraw[];
  Smem& S = *reinterpret_cast<Smem*>(smraw);
  cgx::cluster_group cl = cgx::this_cluster();
  const int rank = cl.block_rank();
  const int b = blockIdx.x / CLS;
  const int tid = threadIdx.x;

  Smem* Sp[CLS];
#pragma unroll
  for (int r = 0; r < CLS; ++r)
    Sp[r] = reinterpret_cast<Smem*>(cl.map_shared_rank(&S, r));

  // Load own 32 rows of support (padded); zero replicated hidden states.
  for (int i = tid; i < NP * Nn; i += NT) {
    const int row = i >> 7, col = i & 127;
    S.P[row * PST + col] = support[(rank * NP + row) * Nn + col];
  }
  for (int i = tid; i < Nn * Un; i += NT) {
    S.h0[i] = 0.f;
    S.h1[i] = 0.f;
  }

  const int tlast = seq_len[b] - 1;  // same for all ranks of this cluster

  for (int t = 0; t <= tlast; ++t) {
    const float4* xt = reinterpret_cast<const float4*>(
        x_all + ((size_t)b * Tn + t) * (Nn * DINn));
    reinterpret_cast<float4*>(S.xb)[tid] = xt[tid];  // 512 float4 = full frame
    cell<DINn>(cl, S, Sp, tid, rank, S.xb, S.h0, W0g, b0g, W0c, b0c);
    cell<Un>(cl, S, Sp, tid, rank, S.h0, S.h1, W1g, b1g, W1c, b1c);
  }

  cl.sync();  // all h1 scatters visible in rank 0's copy

  if (rank == 0) {
    // classifier: max_n( relu(h1[n]) @ Wfc + bfc ); z1 is dead here, use as scratch
    const int n = tid >> 2;
    const int c = tid & 3;
    float a = 0.f;
#pragma unroll 8
    for (int u = 0; u < Un; ++u)
      a = fmaf(fmaxf(S.h1[n * Un + u], 0.f), Wfc[u * Cn + c], a);
    S.z1[n * Cn + c] = a + bfc[c];
    __syncthreads();
    if (tid < Cn) {
      float m = S.z1[tid];
      for (int n2 = 1; n2 < Nn; ++n2) m = fmaxf(m, S.z1[n2 * Cn + tid]);
      out[b * Cn + tid] = m;
    }
  }
}

extern "C" void kernel_launch(void* const* d_in, const int* in_sizes, int n_in,
                              void* d_out, int out_size) {
  const float* x   = (const float*)d_in[0];
  const int*   sl  = (const int*)d_in[1];
  const float* sup = (const float*)d_in[2];
  const float* W0g = (const float*)d_in[3];
  const float* b0g = (const float*)d_in[4];
  const float* W0c = (const float*)d_in[5];
  const float* b0c = (const float*)d_in[6];
  const float* W1g = (const float*)d_in[7];
  const float* b1g = (const float*)d_in[8];
  const float* W1c = (const float*)d_in[9];
  const float* b1c = (const float*)d_in[10];
  const float* Wfc = (const float*)d_in[11];
  const float* bfc = (const float*)d_in[12];
  float* out = (float*)d_out;

  const size_t smem = sizeof(Smem);
  cudaFuncSetAttribute(dcgru_kernel,
                       cudaFuncAttributeMaxDynamicSharedMemorySize, (int)smem);
  dcgru_kernel<<<Bn * CLS, NT, smem>>>(x, sl, sup, W0g, b0g, W0c, b0c,
                                       W1g, b1g, W1c, b1c, Wfc, bfc, out);
}

// round 8
// speedup vs baseline: 3.2293x; 1.1911x over previous
#include <cuda_runtime.h>
#include <cooperative_groups.h>
#include <math.h>

namespace cgx = cooperative_groups;
#define DEVINL __device__ __forceinline__

namespace {

constexpr int Bn   = 32;   // batch
constexpr int Tn   = 256;  // timesteps
constexpr int Nn   = 128;  // nodes
constexpr int DINn = 16;   // input features
constexpr int Un   = 64;   // hidden units
constexpr int Cn   = 4;    // classes
constexpr int CLS  = 4;    // cluster size (CTAs per batch)
constexpr int NP   = 32;   // nodes owned per CTA
constexpr int NT   = 512;  // threads per CTA
constexpr int TST  = 36;   // transposed-z2 row stride (mult of 4 for LDS.128)

struct Smem {
  float P[NP * Nn];     // own 32 rows of support          (16 KB)
  float h0[Nn * Un];    // replicated hidden, layer 0      (32 KB)
  float h1[Nn * Un];    // replicated hidden, layer 1      (32 KB)
  float xb[Nn * DINn];  // current input frame             ( 8 KB)
  float rh[Nn * Un];    // replicated r*h                  (32 KB)
  float z1[Nn * Nn];    // full P@z, row stride = CIN      (64 KB)
  float t2[Nn * TST];   // z2 transposed [c][n_local]      (18 KB)
  float ub[NP * Un];    // own update gate                 ( 8 KB)
};                      // 53760 floats = 215040 B

// ---- hop 1: z1[n][:] = sum_k P[n][k] z0[k][:]  for own nodes.
// 8 warps active; warp = 4 nodes, lane = 4 channels. Result (row-major)
// scattered to all 4 ranks' z1.
template <int CH0>
DEVINL void diffuse1(Smem& S, Smem* const* Sp, int tid, int rank,
                     const float* __restrict__ s0, const float* __restrict__ s1) {
  constexpr int CIN = CH0 + Un;
  if (tid >= 256) return;
  const int w = tid >> 5, lane = tid & 31;
  const int c4 = lane * 4;
  if (c4 >= CIN) return;
  const int n0 = w * 4;
  const float* Pb = &S.P[n0 * Nn];
  float a[4][4];
#pragma unroll
  for (int i = 0; i < 4; ++i)
#pragma unroll
    for (int j = 0; j < 4; ++j) a[i][j] = 0.f;
#pragma unroll 4
  for (int k = 0; k < Nn; ++k) {
    const float* src = (c4 < CH0) ? (s0 + k * CH0 + c4)
                                  : (s1 + k * Un + (c4 - CH0));
    const float4 zf = *reinterpret_cast<const float4*>(src);
    const float zc[4] = {zf.x, zf.y, zf.z, zf.w};
    const float p[4] = {Pb[k], Pb[Nn + k], Pb[2 * Nn + k], Pb[3 * Nn + k]};
#pragma unroll
    for (int i = 0; i < 4; ++i)
#pragma unroll
      for (int j = 0; j < 4; ++j) a[i][j] = fmaf(p[i], zc[j], a[i][j]);
  }
  const int ng0 = rank * NP + n0;
#pragma unroll
  for (int r = 0; r < CLS; ++r) {
    float* zr = Sp[r]->z1;
#pragma unroll
    for (int i = 0; i < 4; ++i)
      *reinterpret_cast<float4*>(&zr[(ng0 + i) * CIN + c4]) =
          make_float4(a[i][0], a[i][1], a[i][2], a[i][3]);
  }
}

// ---- hop 2: z2[n][:] = 2 P z1 - z0 for own nodes; stored TRANSPOSED in t2[c][n].
template <int CH0>
DEVINL void diffuse2(Smem& S, int tid, int rank,
                     const float* __restrict__ s0, const float* __restrict__ s1) {
  constexpr int CIN = CH0 + Un;
  if (tid >= 256) return;
  const int w = tid >> 5, lane = tid & 31;
  const int c4 = lane * 4;
  if (c4 >= CIN) return;
  const int n0 = w * 4;
  const int ng0 = rank * NP + n0;
  const float* Pb = &S.P[n0 * Nn];
  float a[4][4];
#pragma unroll
  for (int i = 0; i < 4; ++i)
#pragma unroll
    for (int j = 0; j < 4; ++j) a[i][j] = 0.f;
#pragma unroll 4
  for (int k = 0; k < Nn; ++k) {
    const float4 zf = *reinterpret_cast<const float4*>(&S.z1[k * CIN + c4]);
    const float zc[4] = {zf.x, zf.y, zf.z, zf.w};
    const float p[4] = {Pb[k], Pb[Nn + k], Pb[2 * Nn + k], Pb[3 * Nn + k]};
#pragma unroll
    for (int i = 0; i < 4; ++i)
#pragma unroll
      for (int j = 0; j < 4; ++j) a[i][j] = fmaf(p[i], zc[j], a[i][j]);
  }
  float z0[4][4];
#pragma unroll
  for (int i = 0; i < 4; ++i) {
    const float* src = (c4 < CH0) ? (s0 + (ng0 + i) * CH0 + c4)
                                  : (s1 + (ng0 + i) * Un + (c4 - CH0));
    const float4 zf = *reinterpret_cast<const float4*>(src);
    z0[i][0] = zf.x; z0[i][1] = zf.y; z0[i][2] = zf.z; z0[i][3] = zf.w;
  }
#pragma unroll
  for (int j = 0; j < 4; ++j)
    *reinterpret_cast<float4*>(&S.t2[(c4 + j) * TST + n0]) =
        make_float4(2.f * a[0][j] - z0[0][j], 2.f * a[1][j] - z0[1][j],
                    2.f * a[2][j] - z0[2][j], 2.f * a[3][j] - z0[3][j]);
}

// ---- projection: acc[i] = sum_{c,m} z_m[n0+i][c] * W[c*3+m][oc].
// Thread = (output column oc, node group of NPT). W loads lane-coalesced.
template <int CH0, int COUT>
DEVINL void accum(Smem& S, int tid, int rank, const float* __restrict__ W,
                  const float* __restrict__ s0, const float* __restrict__ s1,
                  float* __restrict__ acc) {
  constexpr int CIN = CH0 + Un;
  constexpr int NPT = NP * COUT / NT;  // 8 (COUT=128) or 4 (COUT=64)
  const int oc = tid & (COUT - 1);
  const int n0 = (tid / COUT) * NPT;
  const int ng0 = rank * NP + n0;
#pragma unroll 2
  for (int c = 0; c < CIN; ++c) {
    const float w0 = W[(3 * c + 0) * COUT + oc];
    const float w1 = W[(3 * c + 1) * COUT + oc];
    const float w2 = W[(3 * c + 2) * COUT + oc];
    float t2v[NPT];
    const float4 ta = *reinterpret_cast<const float4*>(&S.t2[c * TST + n0]);
    t2v[0] = ta.x; t2v[1] = ta.y; t2v[2] = ta.z; t2v[3] = ta.w;
    if (NPT == 8) {
      const float4 tb = *reinterpret_cast<const float4*>(&S.t2[c * TST + n0 + 4]);
      t2v[4] = tb.x; t2v[5] = tb.y; t2v[6] = tb.z; t2v[7] = tb.w;
    }
    const float* z0base = (c < CH0) ? (s0 + ng0 * CH0 + c)
                                    : (s1 + ng0 * Un + (c - CH0));
    const int z0str = (c < CH0) ? CH0 : Un;
#pragma unroll
    for (int i = 0; i < NPT; ++i) {
      const float z0 = z0base[i * z0str];
      const float z1v = S.z1[(ng0 + i) * CIN + c];
      acc[i] = fmaf(z0, w0, fmaf(z1v, w1, fmaf(t2v[i], w2, acc[i])));
    }
  }
}

// ---- one DCGRU cell, cluster-cooperative.
template <int CH0>
DEVINL void cell(cgx::cluster_group& cl, Smem& S, Smem* const* Sp, int tid,
                 int rank, const float* __restrict__ s0, float* __restrict__ h,
                 const float* __restrict__ Wg, const float* __restrict__ bg,
                 const float* __restrict__ Wc, const float* __restrict__ bc) {
  const size_t hoff = (size_t)((const char*)h - (const char*)&S);

  // ================= gate =================
  cl.sync();  // inputs visible everywhere; z1 free for reuse
  diffuse1<CH0>(S, Sp, tid, rank, s0, h);
  cl.sync();  // z1 fully assembled in every rank
  diffuse2<CH0>(S, tid, rank, s0, h);
  __syncthreads();
  {
    float acc[8];
#pragma unroll
    for (int i = 0; i < 8; ++i) acc[i] = 0.f;
    accum<CH0, 128>(S, tid, rank, Wg, s0, h, acc);
    const int oc = tid & 127;
    const int n0 = (tid >> 7) * 8;
    const int ng0 = rank * NP + n0;
    const float bias = bg[oc];
    float v[8];
#pragma unroll
    for (int i = 0; i < 8; ++i)
      v[i] = 1.f / (1.f + __expf(-(acc[i] + bias)));
    if (oc < Un) {  // r-part -> rh, scattered to all ranks
      float rv[8];
#pragma unroll
      for (int i = 0; i < 8; ++i) rv[i] = v[i] * h[(ng0 + i) * Un + oc];
#pragma unroll
      for (int r = 0; r < CLS; ++r) {
        float* d = Sp[r]->rh;
#pragma unroll
        for (int i = 0; i < 8; ++i) d[(ng0 + i) * Un + oc] = rv[i];
      }
    } else {  // u-part -> local ub
      const int ou = oc - Un;
#pragma unroll
      for (int i = 0; i < 8; ++i) S.ub[(n0 + i) * Un + ou] = v[i];
    }
  }

  // ================= candidate + update =================
  cl.sync();  // rh gathered everywhere; all ranks past gate accum
  diffuse1<CH0>(S, Sp, tid, rank, s0, S.rh);
  cl.sync();
  diffuse2<CH0>(S, tid, rank, s0, S.rh);
  __syncthreads();
  {
    float acc[4] = {0.f, 0.f, 0.f, 0.f};
    accum<CH0, 64>(S, tid, rank, Wc, s0, S.rh, acc);
    const int oc = tid & 63;
    const int n0 = (tid >> 6) * 4;
    const int ng0 = rank * NP + n0;
    const float bias = bc[oc];
    float hn[4];
#pragma unroll
    for (int i = 0; i < 4; ++i) {
      const float cv = tanhf(acc[i] + bias);
      const float u = S.ub[(n0 + i) * Un + oc];
      hn[i] = u * h[(ng0 + i) * Un + oc] + (1.f - u) * cv;
    }
#pragma unroll
    for (int r = 0; r < CLS; ++r) {
      float* hp = reinterpret_cast<float*>((char*)Sp[r] + hoff);
#pragma unroll
      for (int i = 0; i < 4; ++i) hp[(ng0 + i) * Un + oc] = hn[i];
    }
  }
}

}  // namespace

__global__ void __launch_bounds__(NT, 1) __cluster_dims__(CLS, 1, 1)
dcgru_kernel(
    const float* __restrict__ x_all,   // (B,T,N,DIN)
    const int* __restrict__ seq_len,   // (B)
    const float* __restrict__ support, // (N,N)
    const float* __restrict__ W0g, const float* __restrict__ b0g,
    const float* __restrict__ W0c, const float* __restrict__ b0c,
    const float* __restrict__ W1g, const float* __restrict__ b1g,
    const float* __restrict__ W1c, const float* __restrict__ b1c,
    const float* __restrict__ Wfc, const float* __restrict__ bfc,
    float* __restrict__ out) {         // (B,C)
  extern __shared__ float smraw[];
  Smem& S = *reinterpret_cast<Smem*>(smraw);
  cgx::cluster_group cl = cgx::this_cluster();
  const int rank = cl.block_rank();
  const int b = blockIdx.x / CLS;
  const int tid = threadIdx.x;

  Smem* Sp[CLS];
#pragma unroll
  for (int r = 0; r < CLS; ++r)
    Sp[r] = reinterpret_cast<Smem*>(cl.map_shared_rank(&S, r));

  // Load own 32 rows of support; zero replicated hidden states.
  for (int i = tid; i < NP * Nn; i += NT)
    S.P[i] = support[rank * NP * Nn + i];
  for (int i = tid; i < Nn * Un; i += NT) {
    S.h0[i] = 0.f;
    S.h1[i] = 0.f;
  }

  const int tlast = seq_len[b] - 1;  // uniform across the cluster

  for (int t = 0; t <= tlast; ++t) {
    const float4* xt = reinterpret_cast<const float4*>(
        x_all + ((size_t)b * Tn + t) * (Nn * DINn));
    reinterpret_cast<float4*>(S.xb)[tid] = xt[tid];  // full frame
    cell<DINn>(cl, S, Sp, tid, rank, S.xb, S.h0, W0g, b0g, W0c, b0c);
    cell<Un>(cl, S, Sp, tid, rank, S.h0, S.h1, W1g, b1g, W1c, b1c);
  }

  cl.sync();  // all h1 scatters visible in rank 0's copy

  if (rank == 0) {
    // classifier: max_n( relu(h1[n]) @ Wfc + bfc ); z1 is dead, use as scratch
    const int n = tid >> 2;
    const int c = tid & 3;
    float a = 0.f;
#pragma unroll 8
    for (int u = 0; u < Un; ++u)
      a = fmaf(fmaxf(S.h1[n * Un + u], 0.f), Wfc[u * Cn + c], a);
    S.z1[n * Cn + c] = a + bfc[c];
    __syncthreads();
    if (tid < Cn) {
      float m = S.z1[tid];
      for (int n2 = 1; n2 < Nn; ++n2) m = fmaxf(m, S.z1[n2 * Cn + tid]);
      out[b * Cn + tid] = m;
    }
  }
}

extern "C" void kernel_launch(void* const* d_in, const int* in_sizes, int n_in,
                              void* d_out, int out_size) {
  const float* x   = (const float*)d_in[0];
  const int*   sl  = (const int*)d_in[1];
  const float* sup = (const float*)d_in[2];
  const float* W0g = (const float*)d_in[3];
  const float* b0g = (const float*)d_in[4];
  const float* W0c = (const float*)d_in[5];
  const float* b0c = (const float*)d_in[6];
  const float* W1g = (const float*)d_in[7];
  const float* b1g = (const float*)d_in[8];
  const float* W1c = (const float*)d_in[9];
  const float* b1c = (const float*)d_in[10];
  const float* Wfc = (const float*)d_in[11];
  const float* bfc = (const float*)d_in[12];
  float* out = (float*)d_out;

  const size_t smem = sizeof(Smem);
  cudaFuncSetAttribute(dcgru_kernel,
                       cudaFuncAttributeMaxDynamicSharedMemorySize, (int)smem);
  dcgru_kernel<<<Bn * CLS, NT, smem>>>(x, sl, sup, W0g, b0g, W0c, b0c,
                                       W1g, b1g, W1c, b1c, Wfc, bfc, out);
}

// round 9
// speedup vs baseline: 4.6166x; 1.4296x over previous
#include <cuda_runtime.h>
#include <cooperative_groups.h>
#include <math.h>

namespace cgx = cooperative_groups;
#define DEVINL __device__ __forceinline__

namespace {

constexpr int Bn   = 32;   // batch
constexpr int Tn   = 256;  // timesteps
constexpr int Nn   = 128;  // nodes
constexpr int DINn = 16;   // input features
constexpr int Un   = 64;   // hidden units
constexpr int Cn   = 4;    // classes
constexpr int CLS  = 4;    // cluster size (CTAs per batch)
constexpr int NP   = 32;   // nodes owned per CTA
constexpr int NT   = 512;  // threads per CTA

// All activation buffers are TRANSPOSED: t[c][n], row stride = Nn (or NP),
// with a 3-bit XOR swizzle on the float4-granule index to keep LDS
// conflict-free when lane-adjacent rows are accessed at the same column.
struct Smem {
  float P[NP * Nn];     // own 32 rows of support, row-major (k contiguous)
  float tx[DINn * Nn];  // transposed input frame        ( 8 KB)
  float th0[Un * Nn];   // transposed hidden, layer 0    (32 KB)
  float th1[Un * Nn];   // transposed hidden, layer 1    (32 KB)
  float trh[Un * Nn];   // transposed r*h                (32 KB)
  float t1[Nn * Nn];    // hop1 result [c][n global]     (64 KB)
  float t2[Nn * NP];    // hop2 result [c][n local]      (16 KB)
  float ub[Un * NP];    // update gate [u][n local]      ( 8 KB)
};                      // 53248 floats = 212992 B

DEVINL int key8(int c) { return (c >> 2) & 7; }

// row base + swizzle key for concat channel c (x-part then h-part)
template <int CH0>
DEVINL const float* zrow(const float* __restrict__ s0t,
                         const float* __restrict__ s1t, int c, int& key) {
  if (c < CH0) { key = key8(c); return s0t + c * Nn; }
  const int ch = c - CH0;
  key = key8(ch);
  return s1t + ch * Nn;
}

// ---- hop 1: t1[c][n] = sum_k P[n][k] z[k][c], own nodes, scattered to all
// ranks. 8 warps; warp = 4 nodes, lane = 4 channels; vector dot over k.
template <int CH0>
DEVINL void hop1(Smem& S, Smem* const* Sp, int tid, int rank,
                 const float* __restrict__ s0t, const float* __restrict__ s1t) {
  constexpr int CIN = CH0 + Un;
  if (tid >= 256) return;
  const int lane = tid & 31;
  const int c4 = lane * 4;
  if (c4 >= CIN) return;
  const int n0 = (tid >> 5) * 4;
  const float* Pr0 = &S.P[(n0 + 0) * Nn];
  const float* Pr1 = &S.P[(n0 + 1) * Nn];
  const float* Pr2 = &S.P[(n0 + 2) * Nn];
  const float* Pr3 = &S.P[(n0 + 3) * Nn];
  const float* zr[4];
  int zk[4];
#pragma unroll
  for (int j = 0; j < 4; ++j) zr[j] = zrow<CH0>(s0t, s1t, c4 + j, zk[j]);
  float a[4][4];
#pragma unroll
  for (int i = 0; i < 4; ++i)
#pragma unroll
    for (int j = 0; j < 4; ++j) a[i][j] = 0.f;
#pragma unroll 2
  for (int k = 0; k < Nn; k += 4) {
    const int g = k >> 2;
    float4 z[4];
#pragma unroll
    for (int j = 0; j < 4; ++j)
      z[j] = *reinterpret_cast<const float4*>(zr[j] + ((g ^ zk[j]) << 2));
    const float4 p0 = *reinterpret_cast<const float4*>(Pr0 + k);
    const float4 p1 = *reinterpret_cast<const float4*>(Pr1 + k);
    const float4 p2 = *reinterpret_cast<const float4*>(Pr2 + k);
    const float4 p3 = *reinterpret_cast<const float4*>(Pr3 + k);
#pragma unroll
    for (int j = 0; j < 4; ++j) {
      a[0][j] = fmaf(p0.x, z[j].x, fmaf(p0.y, z[j].y,
                fmaf(p0.z, z[j].z, fmaf(p0.w, z[j].w, a[0][j]))));
      a[1][j] = fmaf(p1.x, z[j].x, fmaf(p1.y, z[j].y,
                fmaf(p1.z, z[j].z, fmaf(p1.w, z[j].w, a[1][j]))));
      a[2][j] = fmaf(p2.x, z[j].x, fmaf(p2.y, z[j].y,
                fmaf(p2.z, z[j].z, fmaf(p2.w, z[j].w, a[2][j]))));
      a[3][j] = fmaf(p3.x, z[j].x, fmaf(p3.y, z[j].y,
                fmaf(p3.z, z[j].z, fmaf(p3.w, z[j].w, a[3][j]))));
    }
  }
  const int ng0 = rank * NP + n0;
  const int gw = ng0 >> 2;
  const int tk = lane & 7;  // == key8(c4+j) for all j
#pragma unroll
  for (int j = 0; j < 4; ++j) {
    const int off = (c4 + j) * Nn + ((gw ^ tk) << 2);
    const float4 v = make_float4(a[0][j], a[1][j], a[2][j], a[3][j]);
#pragma unroll
    for (int r = 0; r < CLS; ++r)
      *reinterpret_cast<float4*>(&Sp[r]->t1[off]) = v;
  }
}

// ---- hop 2: t2[c][n] = 2 * sum_k P[n][k] t1[c][k] - z0[c][n], own nodes.
template <int CH0>
DEVINL void hop2(Smem& S, int tid, int rank,
                 const float* __restrict__ s0t, const float* __restrict__ s1t) {
  constexpr int CIN = CH0 + Un;
  if (tid >= 256) return;
  const int lane = tid & 31;
  const int c4 = lane * 4;
  if (c4 >= CIN) return;
  const int n0 = (tid >> 5) * 4;
  const int ng0 = rank * NP + n0;
  const int tk = lane & 7;
  const float* Pr0 = &S.P[(n0 + 0) * Nn];
  const float* Pr1 = &S.P[(n0 + 1) * Nn];
  const float* Pr2 = &S.P[(n0 + 2) * Nn];
  const float* Pr3 = &S.P[(n0 + 3) * Nn];
  const float* t1r[4];
#pragma unroll
  for (int j = 0; j < 4; ++j) t1r[j] = &S.t1[(c4 + j) * Nn];
  float a[4][4];
#pragma unroll
  for (int i = 0; i < 4; ++i)
#pragma unroll
    for (int j = 0; j < 4; ++j) a[i][j] = 0.f;
#pragma unroll 2
  for (int k = 0; k < Nn; k += 4) {
    const int g = (k >> 2) ^ tk;
    float4 z[4];
#pragma unroll
    for (int j = 0; j < 4; ++j)
      z[j] = *reinterpret_cast<const float4*>(t1r[j] + (g << 2));
    const float4 p0 = *reinterpret_cast<const float4*>(Pr0 + k);
    const float4 p1 = *reinterpret_cast<const float4*>(Pr1 + k);
    const float4 p2 = *reinterpret_cast<const float4*>(Pr2 + k);
    const float4 p3 = *reinterpret_cast<const float4*>(Pr3 + k);
#pragma unroll
    for (int j = 0; j < 4; ++j) {
      a[0][j] = fmaf(p0.x, z[j].x, fmaf(p0.y, z[j].y,
                fmaf(p0.z, z[j].z, fmaf(p0.w, z[j].w, a[0][j]))));
      a[1][j] = fmaf(p1.x, z[j].x, fmaf(p1.y, z[j].y,
                fmaf(p1.z, z[j].z, fmaf(p1.w, z[j].w, a[1][j]))));
      a[2][j] = fmaf(p2.x, z[j].x, fmaf(p2.y, z[j].y,
                fmaf(p2.z, z[j].z, fmaf(p2.w, z[j].w, a[2][j]))));
      a[3][j] = fmaf(p3.x, z[j].x, fmaf(p3.y, z[j].y,
                fmaf(p3.z, z[j].z, fmaf(p3.w, z[j].w, a[3][j]))));
    }
  }
  const int g0 = ng0 >> 2;
  const int gl = n0 >> 2;
#pragma unroll
  for (int j = 0; j < 4; ++j) {
    int zk;
    const float* zr = zrow<CH0>(s0t, s1t, c4 + j, zk);
    const float4 z0 = *reinterpret_cast<const float4*>(zr + ((g0 ^ zk) << 2));
    *reinterpret_cast<float4*>(&S.t2[(c4 + j) * NP + ((gl ^ tk) << 2)]) =
        make_float4(2.f * a[0][j] - z0.x, 2.f * a[1][j] - z0.y,
                    2.f * a[2][j] - z0.z, 2.f * a[3][j] - z0.w);
  }
}

// ---- projection: acc[i] += sum_{c,m} z_m[c][n0+i] * W[c*3+m][oc].
// thread = (oc = tid/(NT/COUT), node block); all z loads are broadcast LDS.128.
template <int CH0, int COUT, int NPT>
DEVINL void accum(Smem& S, int tid, int rank, const float* __restrict__ W,
                  const float* __restrict__ s0t, const float* __restrict__ s1t,
                  float* __restrict__ acc) {
  constexpr int CIN = CH0 + Un;
  constexpr int LPO = NT / COUT;  // threads per output column
  const int oc = tid / LPO;
  const int n0 = (tid % LPO) * NPT;
  const int g1 = (rank * NP + n0) >> 2;
  const int g2 = n0 >> 2;
#pragma unroll 4
  for (int c = 0; c < CIN; ++c) {
    const float w0 = W[(3 * c + 0) * COUT + oc];
    const float w1 = W[(3 * c + 1) * COUT + oc];
    const float w2 = W[(3 * c + 2) * COUT + oc];
    const int k = key8(c);
    int zk;
    const float* zr = zrow<CH0>(s0t, s1t, c, zk);
    const float* t1r = &S.t1[c * Nn];
    const float* t2r = &S.t2[c * NP];
#pragma unroll
    for (int q = 0; q < NPT / 4; ++q) {
      const float4 z0 = *reinterpret_cast<const float4*>(zr + (((g1 + q) ^ zk) << 2));
      const float4 z1 = *reinterpret_cast<const float4*>(t1r + (((g1 + q) ^ k) << 2));
      const float4 z2 = *reinterpret_cast<const float4*>(t2r + (((g2 + q) ^ k) << 2));
      float* av = acc + q * 4;
      av[0] = fmaf(z0.x, w0, fmaf(z1.x, w1, fmaf(z2.x, w2, av[0])));
      av[1] = fmaf(z0.y, w0, fmaf(z1.y, w1, fmaf(z2.y, w2, av[1])));
      av[2] = fmaf(z0.z, w0, fmaf(z1.z, w1, fmaf(z2.z, w2, av[2])));
      av[3] = fmaf(z0.w, w0, fmaf(z1.w, w1, fmaf(z2.w, w2, av[3])));
    }
  }
}

// ---- one DCGRU cell, cluster-cooperative; ht = this layer's transposed h.
template <int CH0>
DEVINL void cell(cgx::cluster_group& cl, Smem& S, Smem* const* Sp, int tid,
                 int rank, const float* __restrict__ s0t, float* __restrict__ ht,
                 const float* __restrict__ Wg, const float* __restrict__ bg,
                 const float* __restrict__ Wc, const float* __restrict__ bc) {
  const size_t hoff = (size_t)((const char*)ht - (const char*)&S);

  // ================= gate =================
  cl.sync();  // inputs visible everywhere; t1 free for reuse
  hop1<CH0>(S, Sp, tid, rank, s0t, ht);
  cl.sync();  // t1 fully assembled in every rank
  hop2<CH0>(S, tid, rank, s0t, ht);
  __syncthreads();
  {
    float acc[8];
#pragma unroll
    for (int i = 0; i < 8; ++i) acc[i] = 0.f;
    accum<CH0, 128, 8>(S, tid, rank, Wg, s0t, ht, acc);
    const int oc = tid >> 2;
    const int n0 = (tid & 3) * 8;
    const int ng0 = rank * NP + n0;
    const float bias = bg[oc];
    float v[8];
#pragma unroll
    for (int i = 0; i < 8; ++i)
      v[i] = 1.f / (1.f + __expf(-(acc[i] + bias)));
    if (oc < Un) {  // r-part -> trh (transposed), scattered to all ranks
      const int k = key8(oc);
      const int g = ng0 >> 2;
      const float* hr = ht + oc * Nn;
      const float4 h0 = *reinterpret_cast<const float4*>(hr + ((g ^ k) << 2));
      const float4 h1 = *reinterpret_cast<const float4*>(hr + (((g + 1) ^ k) << 2));
      const float4 r0 = make_float4(v[0] * h0.x, v[1] * h0.y, v[2] * h0.z, v[3] * h0.w);
      const float4 r1 = make_float4(v[4] * h1.x, v[5] * h1.y, v[6] * h1.z, v[7] * h1.w);
#pragma unroll
      for (int r = 0; r < CLS; ++r) {
        float* base = &Sp[r]->trh[oc * Nn];
        *reinterpret_cast<float4*>(base + ((g ^ k) << 2)) = r0;
        *reinterpret_cast<float4*>(base + (((g + 1) ^ k) << 2)) = r1;
      }
    } else {  // u-part -> local ub (transposed)
      const int ou = oc - Un;
      const int ku = key8(ou);
      const int gl = n0 >> 2;
      float* ur = &S.ub[ou * NP];
      *reinterpret_cast<float4*>(ur + ((gl ^ ku) << 2)) =
          make_float4(v[0], v[1], v[2], v[3]);
      *reinterpret_cast<float4*>(ur + (((gl + 1) ^ ku) << 2)) =
          make_float4(v[4], v[5], v[6], v[7]);
    }
  }

  // ================= candidate + update =================
  cl.sync();  // trh gathered everywhere; all ranks past gate accum
  hop1<CH0>(S, Sp, tid, rank, s0t, S.trh);
  cl.sync();
  hop2<CH0>(S, tid, rank, s0t, S.trh);
  __syncthreads();
  {
    float acc[4] = {0.f, 0.f, 0.f, 0.f};
    accum<CH0, 64, 4>(S, tid, rank, Wc, s0t, S.trh, acc);
    const int oc = tid >> 3;
    const int n0 = (tid & 7) * 4;
    const int ng0 = rank * NP + n0;
    const int k = key8(oc);
    const float bias = bc[oc];
    const float4 uu = *reinterpret_cast<const float4*>(
        &S.ub[oc * NP] + (((n0 >> 2) ^ k) << 2));
    const int go = ((ng0 >> 2) ^ k) << 2;
    const float4 hh = *reinterpret_cast<const float4*>(ht + oc * Nn + go);
    float4 hn;
    hn.x = uu.x * hh.x + (1.f - uu.x) * tanhf(acc[0] + bias);
    hn.y = uu.y * hh.y + (1.f - uu.y) * tanhf(acc[1] + bias);
    hn.z = uu.z * hh.z + (1.f - uu.z) * tanhf(acc[2] + bias);
    hn.w = uu.w * hh.w + (1.f - uu.w) * tanhf(acc[3] + bias);
#pragma unroll
    for (int r = 0; r < CLS; ++r) {
      float* hp = reinterpret_cast<float*>((char*)Sp[r] + hoff);
      *reinterpret_cast<float4*>(hp + oc * Nn + go) = hn;
    }
  }
}

}  // namespace

__global__ void __launch_bounds__(NT, 1) __cluster_dims__(CLS, 1, 1)
dcgru_kernel(
    const float* __restrict__ x_all,   // (B,T,N,DIN)
    const int* __restrict__ seq_len,   // (B)
    const float* __restrict__ support, // (N,N)
    const float* __restrict__ W0g, const float* __restrict__ b0g,
    const float* __restrict__ W0c, const float* __restrict__ b0c,
    const float* __restrict__ W1g, const float* __restrict__ b1g,
    const float* __restrict__ W1c, const float* __restrict__ b1c,
    const float* __restrict__ Wfc, const float* __restrict__ bfc,
    float* __restrict__ out) {         // (B,C)
  extern __shared__ float smraw[];
  Smem& S = *reinterpret_cast<Smem*>(smraw);
  cgx::cluster_group cl = cgx::this_cluster();
  const int rank = cl.block_rank();
  const int b = blockIdx.x / CLS;
  const int tid = threadIdx.x;

  Smem* Sp[CLS];
#pragma unroll
  for (int r = 0; r < CLS; ++r)
    Sp[r] = reinterpret_cast<Smem*>(cl.map_shared_rank(&S, r));

  // Load own 32 rows of support; zero transposed hidden states.
  for (int i = tid; i < NP * Nn; i += NT)
    S.P[i] = support[rank * NP * Nn + i];
  for (int i = tid; i < Un * Nn; i += NT) {
    S.th0[i] = 0.f;
    S.th1[i] = 0.f;
  }

  const int tlast = seq_len[b] - 1;  // uniform across the cluster

  for (int t = 0; t <= tlast; ++t) {
    // stage current frame TRANSPOSED: tx[c][n] (swizzled)
    const float4 xv = reinterpret_cast<const float4*>(
        x_all + ((size_t)b * Tn + t) * (Nn * DINn))[tid];
    {
      const int n = tid >> 2;
      const int c0 = (tid & 3) * 4;
      const int k = tid & 3;  // key8(c0+j) for all j<4
      const int base = ((n >> 2) ^ k) * 4 + (n & 3);
      S.tx[(c0 + 0) * Nn + base] = xv.x;
      S.tx[(c0 + 1) * Nn + base] = xv.y;
      S.tx[(c0 + 2) * Nn + base] = xv.z;
      S.tx[(c0 + 3) * Nn + base] = xv.w;
    }
    cell<DINn>(cl, S, Sp, tid, rank, S.tx, S.th0, W0g, b0g, W0c, b0c);
    cell<Un>(cl, S, Sp, tid, rank, S.th0, S.th1, W1g, b1g, W1c, b1c);
  }

  cl.sync();  // all th1 scatters visible in rank 0's copy

  if (rank == 0) {
    // classifier: max_n( relu(h1[n]) @ Wfc + bfc ); t1 is dead, use as scratch
    const int n = tid >> 2;
    const int c = tid & 3;
    float a = 0.f;
#pragma unroll 8
    for (int u = 0; u < Un; ++u) {
      const float hv = S.th1[u * Nn + (((n >> 2) ^ key8(u)) << 2) + (n & 3)];
      a = fmaf(fmaxf(hv, 0.f), Wfc[u * Cn + c], a);
    }
    S.t1[n * Cn + c] = a + bfc[c];
    __syncthreads();
    if (tid < Cn) {
      float m = S.t1[tid];
      for (int n2 = 1; n2 < Nn; ++n2) m = fmaxf(m, S.t1[n2 * Cn + tid]);
      out[b * Cn + tid] = m;
    }
  }
}

extern "C" void kernel_launch(void* const* d_in, const int* in_sizes, int n_in,
                              void* d_out, int out_size) {
  const float* x   = (const float*)d_in[0];
  const int*   sl  = (const int*)d_in[1];
  const float* sup = (const float*)d_in[2];
  const float* W0g = (const float*)d_in[3];
  const float* b0g = (const float*)d_in[4];
  const float* W0c = (const float*)d_in[5];
  const float* b0c = (const float*)d_in[6];
  const float* W1g = (const float*)d_in[7];
  const float* b1g = (const float*)d_in[8];
  const float* W1c = (const float*)d_in[9];
  const float* b1c = (const float*)d_in[10];
  const float* Wfc = (const float*)d_in[11];
  const float* bfc = (const float*)d_in[12];
  float* out = (float*)d_out;

  const size_t smem = sizeof(Smem);
  cudaFuncSetAttribute(dcgru_kernel,
                       cudaFuncAttributeMaxDynamicSharedMemorySize, (int)smem);
  dcgru_kernel<<<Bn * CLS, NT, smem>>>(x, sl, sup, W0g, b0g, W0c, b0c,
                                       W1g, b1g, W1c, b1c, Wfc, bfc, out);
}

// round 10
// speedup vs baseline: 4.7335x; 1.0253x over previous
#include <cuda_runtime.h>
#include <cooperative_groups.h>
#include <math.h>

namespace cgx = cooperative_groups;
#define DEVINL __device__ __forceinline__

namespace {

constexpr int Bn   = 32;   // batch
constexpr int Tn   = 256;  // timesteps
constexpr int Nn   = 128;  // nodes
constexpr int DINn = 16;   // input features
constexpr int Un   = 64;   // hidden units
constexpr int Cn   = 4;    // classes
constexpr int CLS  = 4;    // cluster size (CTAs per batch)
constexpr int NP   = 32;   // nodes owned per CTA
constexpr int NT   = 512;  // threads per CTA

typedef unsigned long long ull;

// packed fp32x2 FMA (sm_103a): d.lo += a.lo*b.lo; d.hi += a.hi*b.hi (exact fp32)
DEVINL void fma2(ull& d, ull a, ull b) {
  asm("fma.rn.f32x2 %0, %1, %2, %0;" : "+l"(d) : "l"(a), "l"(b));
}
DEVINL ull dup2(float a) {
  ull r; asm("mov.b64 %0, {%1, %1};" : "=l"(r) : "f"(a)); return r;
}
DEVINL float2 lohi(ull v) {
  float2 r; asm("mov.b64 {%0, %1}, %2;" : "=f"(r.x), "=f"(r.y) : "l"(v)); return r;
}
DEVINL float rsum(ull v) { const float2 t = lohi(v); return t.x + t.y; }

// All activation buffers are TRANSPOSED: t[c][n], row stride = Nn (or NP),
// with a 3-bit XOR swizzle on the float4-granule index.
struct Smem {
  float P[NP * Nn];     // own 32 rows of support, row-major (k contiguous)
  float tx[DINn * Nn];  // transposed input frame        ( 8 KB)
  float th0[Un * Nn];   // transposed hidden, layer 0    (32 KB)
  float th1[Un * Nn];   // transposed hidden, layer 1    (32 KB)
  float trh[Un * Nn];   // transposed r*h                (32 KB)
  float t1[Nn * Nn];    // hop1 result [c][n global]     (64 KB)
  float t2[Nn * NP];    // hop2 result [c][n local]      (16 KB)
  float ub[Un * NP];    // update gate [u][n local]      ( 8 KB)
};                      // 53248 floats = 212992 B

DEVINL int key8(int c) { return (c >> 2) & 7; }

// row base + swizzle key for concat channel c (x-part then h-part)
template <int CH0>
DEVINL const float* zrow(const float* __restrict__ s0t,
                         const float* __restrict__ s1t, int c, int& key) {
  if (c < CH0) { key = key8(c); return s0t + c * Nn; }
  const int ch = c - CH0;
  key = key8(ch);
  return s1t + ch * Nn;
}

// ---- gate hop 1: t1[c][n] = sum_k P[n][k] z[k][c], own nodes, all channels.
// 8 warps; warp = 4 nodes, lane = 4 channels; f32x2 packed over k-pairs.
template <int CH0>
DEVINL void hop1(Smem& S, Smem* const* Sp, int tid, int rank,
                 const float* __restrict__ s0t, const float* __restrict__ s1t) {
  constexpr int CIN = CH0 + Un;
  if (tid >= 256) return;
  const int lane = tid & 31;
  const int c4 = lane * 4;
  if (c4 >= CIN) return;
  const int n0 = (tid >> 5) * 4;
  const float* Pr0 = &S.P[(n0 + 0) * Nn];
  const float* Pr1 = &S.P[(n0 + 1) * Nn];
  const float* Pr2 = &S.P[(n0 + 2) * Nn];
  const float* Pr3 = &S.P[(n0 + 3) * Nn];
  const float* zr[4];
  int zk[4];
#pragma unroll
  for (int j = 0; j < 4; ++j) zr[j] = zrow<CH0>(s0t, s1t, c4 + j, zk[j]);
  ull a2[4][4] = {};
#pragma unroll 2
  for (int k = 0; k < Nn; k += 4) {
    const int g = k >> 2;
    const ulonglong2 p0 = *reinterpret_cast<const ulonglong2*>(Pr0 + k);
    const ulonglong2 p1 = *reinterpret_cast<const ulonglong2*>(Pr1 + k);
    const ulonglong2 p2 = *reinterpret_cast<const ulonglong2*>(Pr2 + k);
    const ulonglong2 p3 = *reinterpret_cast<const ulonglong2*>(Pr3 + k);
#pragma unroll
    for (int j = 0; j < 4; ++j) {
      const ulonglong2 z = *reinterpret_cast<const ulonglong2*>(
          zr[j] + ((g ^ zk[j]) << 2));
      fma2(a2[0][j], p0.x, z.x); fma2(a2[0][j], p0.y, z.y);
      fma2(a2[1][j], p1.x, z.x); fma2(a2[1][j], p1.y, z.y);
      fma2(a2[2][j], p2.x, z.x); fma2(a2[2][j], p2.y, z.y);
      fma2(a2[3][j], p3.x, z.x); fma2(a2[3][j], p3.y, z.y);
    }
  }
  const int ng0 = rank * NP + n0;
  const int gw = ng0 >> 2;
  const int tk = lane & 7;  // == key8(c4+j)
#pragma unroll
  for (int j = 0; j < 4; ++j) {
    const int off = (c4 + j) * Nn + ((gw ^ tk) << 2);
    const float4 v = make_float4(rsum(a2[0][j]), rsum(a2[1][j]),
                                 rsum(a2[2][j]), rsum(a2[3][j]));
#pragma unroll
    for (int r = 0; r < CLS; ++r)
      *reinterpret_cast<float4*>(&Sp[r]->t1[off]) = v;
  }
}

// ---- gate hop 2: t2[c][n] = 2*sum_k P[n][k] t1[c][k] - z0[c][n], all channels.
template <int CH0>
DEVINL void hop2(Smem& S, int tid, int rank,
                 const float* __restrict__ s0t, const float* __restrict__ s1t) {
  constexpr int CIN = CH0 + Un;
  if (tid >= 256) return;
  const int lane = tid & 31;
  const int c4 = lane * 4;
  if (c4 >= CIN) return;
  const int n0 = (tid >> 5) * 4;
  const int ng0 = rank * NP + n0;
  const int tk = lane & 7;
  const float* Pr0 = &S.P[(n0 + 0) * Nn];
  const float* Pr1 = &S.P[(n0 + 1) * Nn];
  const float* Pr2 = &S.P[(n0 + 2) * Nn];
  const float* Pr3 = &S.P[(n0 + 3) * Nn];
  const float* t1r[4];
#pragma unroll
  for (int j = 0; j < 4; ++j) t1r[j] = &S.t1[(c4 + j) * Nn];
  ull a2[4][4] = {};
#pragma unroll 2
  for (int k = 0; k < Nn; k += 4) {
    const int g = (k >> 2) ^ tk;
    const ulonglong2 p0 = *reinterpret_cast<const ulonglong2*>(Pr0 + k);
    const ulonglong2 p1 = *reinterpret_cast<const ulonglong2*>(Pr1 + k);
    const ulonglong2 p2 = *reinterpret_cast<const ulonglong2*>(Pr2 + k);
    const ulonglong2 p3 = *reinterpret_cast<const ulonglong2*>(Pr3 + k);
#pragma unroll
    for (int j = 0; j < 4; ++j) {
      const ulonglong2 z = *reinterpret_cast<const ulonglong2*>(t1r[j] + (g << 2));
      fma2(a2[0][j], p0.x, z.x); fma2(a2[0][j], p0.y, z.y);
      fma2(a2[1][j], p1.x, z.x); fma2(a2[1][j], p1.y, z.y);
      fma2(a2[2][j], p2.x, z.x); fma2(a2[2][j], p2.y, z.y);
      fma2(a2[3][j], p3.x, z.x); fma2(a2[3][j], p3.y, z.y);
    }
  }
  const int g0 = ng0 >> 2;
  const int gl = n0 >> 2;
#pragma unroll
  for (int j = 0; j < 4; ++j) {
    int zk;
    const float* zr = zrow<CH0>(s0t, s1t, c4 + j, zk);
    const float4 z0 = *reinterpret_cast<const float4*>(zr + ((g0 ^ zk) << 2));
    *reinterpret_cast<float4*>(&S.t2[(c4 + j) * NP + ((gl ^ tk) << 2)]) =
        make_float4(2.f * rsum(a2[0][j]) - z0.x, 2.f * rsum(a2[1][j]) - z0.y,
                    2.f * rsum(a2[2][j]) - z0.z, 2.f * rsum(a2[3][j]) - z0.w);
  }
}

// ---- candidate hop 1: only the rh-part channels [CH0, CIN) need recompute;
// the x/h0-part rows of t1 persist from the gate phase. 256 threads:
// thread = (node pair, 4 rh-channels).
template <int CH0>
DEVINL void hop1c(Smem& S, Smem* const* Sp, int tid, int rank) {
  if (tid >= 256) return;
  const int cn = tid & 15;        // rh channel group (64 ch total)
  const int ch4 = cn * 4;         // trh-local channel
  const int tk = cn & 7;          // key8(ch4+j)
  const int n0 = (tid >> 4) * 2;  // local node pair
  const float* Pr0 = &S.P[(n0 + 0) * Nn];
  const float* Pr1 = &S.P[(n0 + 1) * Nn];
  const float* zr[4];
#pragma unroll
  for (int j = 0; j < 4; ++j) zr[j] = &S.trh[(ch4 + j) * Nn];
  ull a2[2][4] = {};
#pragma unroll 2
  for (int k = 0; k < Nn; k += 4) {
    const int g = (k >> 2) ^ tk;
    const ulonglong2 p0 = *reinterpret_cast<const ulonglong2*>(Pr0 + k);
    const ulonglong2 p1 = *reinterpret_cast<const ulonglong2*>(Pr1 + k);
#pragma unroll
    for (int j = 0; j < 4; ++j) {
      const ulonglong2 z = *reinterpret_cast<const ulonglong2*>(zr[j] + (g << 2));
      fma2(a2[0][j], p0.x, z.x); fma2(a2[0][j], p0.y, z.y);
      fma2(a2[1][j], p1.x, z.x); fma2(a2[1][j], p1.y, z.y);
    }
  }
  const int ksd = ((CH0 >> 2) + cn) & 7;  // key8 of destination t1 row
  const int ng0 = rank * NP + n0;
  const int gw = ng0 >> 2, ofs = ng0 & 3;
#pragma unroll
  for (int j = 0; j < 4; ++j) {
    const int off = (CH0 + ch4 + j) * Nn + ((gw ^ ksd) << 2) + ofs;
    const float2 v = make_float2(rsum(a2[0][j]), rsum(a2[1][j]));
#pragma unroll
    for (int r = 0; r < CLS; ++r)
      *reinterpret_cast<float2*>(&Sp[r]->t1[off]) = v;
  }
}

// ---- candidate hop 2: rh-part channels only; t2 x-rows persist from gate.
template <int CH0>
DEVINL void hop2c(Smem& S, int tid, int rank) {
  if (tid >= 256) return;
  const int cn = tid & 15;
  const int ch4 = cn * 4;
  const int tk = cn & 7;
  const int ksd = ((CH0 >> 2) + cn) & 7;
  const int n0 = (tid >> 4) * 2;
  const int ng0 = rank * NP + n0;
  const float* Pr0 = &S.P[(n0 + 0) * Nn];
  const float* Pr1 = &S.P[(n0 + 1) * Nn];
  const float* t1r[4];
#pragma unroll
  for (int j = 0; j < 4; ++j) t1r[j] = &S.t1[(CH0 + ch4 + j) * Nn];
  ull a2[2][4] = {};
#pragma unroll 2
  for (int k = 0; k < Nn; k += 4) {
    const int g = (k >> 2) ^ ksd;
    const ulonglong2 p0 = *reinterpret_cast<const ulonglong2*>(Pr0 + k);
    const ulonglong2 p1 = *reinterpret_cast<const ulonglong2*>(Pr1 + k);
#pragma unroll
    for (int j = 0; j < 4; ++j) {
      const ulonglong2 z = *reinterpret_cast<const ulonglong2*>(t1r[j] + (g << 2));
      fma2(a2[0][j], p0.x, z.x); fma2(a2[0][j], p0.y, z.y);
      fma2(a2[1][j], p1.x, z.x); fma2(a2[1][j], p1.y, z.y);
    }
  }
  const int gw = ng0 >> 2, ofs = ng0 & 3;
  const int gl = n0 >> 2, ofl = n0 & 3;
#pragma unroll
  for (int j = 0; j < 4; ++j) {
    const float2 z0 = *reinterpret_cast<const float2*>(
        &S.trh[(ch4 + j) * Nn + ((gw ^ tk) << 2) + ofs]);
    *reinterpret_cast<float2*>(
        &S.t2[(CH0 + ch4 + j) * NP + ((gl ^ ksd) << 2) + ofl]) =
        make_float2(2.f * rsum(a2[0][j]) - z0.x, 2.f * rsum(a2[1][j]) - z0.y);
  }
}

// ---- projection: acc2[q] packs node pairs; f32x2 FMA with w dups.
template <int CH0, int COUT, int NPT>
DEVINL void accum(Smem& S, int tid, int rank, const float* __restrict__ W,
                  const float* __restrict__ s0t, const float* __restrict__ s1t,
                  ull* __restrict__ acc2) {
  constexpr int CIN = CH0 + Un;
  constexpr int LPO = NT / COUT;  // threads per output column
  const int oc = tid / LPO;
  const int n0 = (tid % LPO) * NPT;
  const int g1 = (rank * NP + n0) >> 2;
  const int g2 = n0 >> 2;
#pragma unroll 4
  for (int c = 0; c < CIN; ++c) {
    const ull w0 = dup2(W[(3 * c + 0) * COUT + oc]);
    const ull w1 = dup2(W[(3 * c + 1) * COUT + oc]);
    const ull w2 = dup2(W[(3 * c + 2) * COUT + oc]);
    const int k = key8(c);
    int zk;
    const float* zr = zrow<CH0>(s0t, s1t, c, zk);
    const float* t1r = &S.t1[c * Nn];
    const float* t2r = &S.t2[c * NP];
#pragma unroll
    for (int q = 0; q < NPT / 4; ++q) {
      const ulonglong2 z0 = *reinterpret_cast<const ulonglong2*>(
          zr + (((g1 + q) ^ zk) << 2));
      const ulonglong2 z1 = *reinterpret_cast<const ulonglong2*>(
          t1r + (((g1 + q) ^ k) << 2));
      const ulonglong2 z2 = *reinterpret_cast<const ulonglong2*>(
          t2r + (((g2 + q) ^ k) << 2));
      fma2(acc2[2 * q + 0], z0.x, w0);
      fma2(acc2[2 * q + 0], z1.x, w1);
      fma2(acc2[2 * q + 0], z2.x, w2);
      fma2(acc2[2 * q + 1], z0.y, w0);
      fma2(acc2[2 * q + 1], z1.y, w1);
      fma2(acc2[2 * q + 1], z2.y, w2);
    }
  }
}

// ---- one DCGRU cell, cluster-cooperative; ht = this layer's transposed h.
template <int CH0>
DEVINL void cell(cgx::cluster_group& cl, Smem& S, Smem* const* Sp, int tid,
                 int rank, const float* __restrict__ s0t, float* __restrict__ ht,
                 const float* __restrict__ Wg, const float* __restrict__ bg,
                 const float* __restrict__ Wc, const float* __restrict__ bc) {
  const size_t hoff = (size_t)((const char*)ht - (const char*)&S);

  // ================= gate =================
  cl.sync();  // inputs visible everywhere; t1 free for reuse
  hop1<CH0>(S, Sp, tid, rank, s0t, ht);
  cl.sync();  // t1 fully assembled in every rank
  hop2<CH0>(S, tid, rank, s0t, ht);
  __syncthreads();
  {
    ull acc2[4] = {0ull, 0ull, 0ull, 0ull};
    accum<CH0, 128, 8>(S, tid, rank, Wg, s0t, ht, acc2);
    float acc[8];
#pragma unroll
    for (int q = 0; q < 4; ++q) {
      const float2 t = lohi(acc2[q]);
      acc[2 * q] = t.x;
      acc[2 * q + 1] = t.y;
    }
    const int oc = tid >> 2;
    const int n0 = (tid & 3) * 8;
    const int ng0 = rank * NP + n0;
    const float bias = bg[oc];
    float v[8];
#pragma unroll
    for (int i = 0; i < 8; ++i)
      v[i] = 1.f / (1.f + __expf(-(acc[i] + bias)));
    if (oc < Un) {  // r-part -> trh (transposed), scattered to all ranks
      const int k = key8(oc);
      const int g = ng0 >> 2;
      const float* hr = ht + oc * Nn;
      const float4 h0 = *reinterpret_cast<const float4*>(hr + ((g ^ k) << 2));
      const float4 h1 = *reinterpret_cast<const float4*>(hr + (((g + 1) ^ k) << 2));
      const float4 r0 = make_float4(v[0] * h0.x, v[1] * h0.y, v[2] * h0.z, v[3] * h0.w);
      const float4 r1 = make_float4(v[4] * h1.x, v[5] * h1.y, v[6] * h1.z, v[7] * h1.w);
#pragma unroll
      for (int r = 0; r < CLS; ++r) {
        float* base = &Sp[r]->trh[oc * Nn];
        *reinterpret_cast<float4*>(base + ((g ^ k) << 2)) = r0;
        *reinterpret_cast<float4*>(base + (((g + 1) ^ k) << 2)) = r1;
      }
    } else {  // u-part -> local ub (transposed)
      const int ou = oc - Un;
      const int ku = key8(ou);
      const int gl = n0 >> 2;
      float* ur = &S.ub[ou * NP];
      *reinterpret_cast<float4*>(ur + ((gl ^ ku) << 2)) =
          make_float4(v[0], v[1], v[2], v[3]);
      *reinterpret_cast<float4*>(ur + (((gl + 1) ^ ku) << 2)) =
          make_float4(v[4], v[5], v[6], v[7]);
    }
  }

  // ================= candidate + update =================
  cl.sync();  // trh gathered everywhere; all ranks past gate accum
  hop1c<CH0>(S, Sp, tid, rank);  // rh-part channels only; x-rows persist
  cl.sync();
  hop2c<CH0>(S, tid, rank);
  __syncthreads();
  {
    ull acc2[2] = {0ull, 0ull};
    accum<CH0, 64, 4>(S, tid, rank, Wc, s0t, S.trh, acc2);
    float acc[4];
    {
      float2 t = lohi(acc2[0]);
      acc[0] = t.x; acc[1] = t.y;
      t = lohi(acc2[1]);
      acc[2] = t.x; acc[3] = t.y;
    }
    const int oc = tid >> 3;
    const int n0 = (tid & 7) * 4;
    const int ng0 = rank * NP + n0;
    const int k = key8(oc);
    const float bias = bc[oc];
    const float4 uu = *reinterpret_cast<const float4*>(
        &S.ub[oc * NP] + (((n0 >> 2) ^ k) << 2));
    const int go = ((ng0 >> 2) ^ k) << 2;
    const float4 hh = *reinterpret_cast<const float4*>(ht + oc * Nn + go);
    float4 hn;
    hn.x = uu.x * hh.x + (1.f - uu.x) * tanhf(acc[0] + bias);
    hn.y = uu.y * hh.y + (1.f - uu.y) * tanhf(acc[1] + bias);
    hn.z = uu.z * hh.z + (1.f - uu.z) * tanhf(acc[2] + bias);
    hn.w = uu.w * hh.w + (1.f - uu.w) * tanhf(acc[3] + bias);
#pragma unroll
    for (int r = 0; r < CLS; ++r) {
      float* hp = reinterpret_cast<float*>((char*)Sp[r] + hoff);
      *reinterpret_cast<float4*>(hp + oc * Nn + go) = hn;
    }
  }
}

}  // namespace

__global__ void __launch_bounds__(NT, 1) __cluster_dims__(CLS, 1, 1)
dcgru_kernel(
    const float* __restrict__ x_all,   // (B,T,N,DIN)
    const int* __restrict__ seq_len,   // (B)
    const float* __restrict__ support, // (N,N)
    const float* __restrict__ W0g, const float* __restrict__ b0g,
    const float* __restrict__ W0c, const float* __restrict__ b0c,
    const float* __restrict__ W1g, const float* __restrict__ b1g,
    const float* __restrict__ W1c, const float* __restrict__ b1c,
    const float* __restrict__ Wfc, const float* __restrict__ bfc,
    float* __restrict__ out) {         // (B,C)
  extern __shared__ float smraw[];
  Smem& S = *reinterpret_cast<Smem*>(smraw);
  cgx::cluster_group cl = cgx::this_cluster();
  const int rank = cl.block_rank();
  const int b = blockIdx.x / CLS;
  const int tid = threadIdx.x;

  Smem* Sp[CLS];
#pragma unroll
  for (int r = 0; r < CLS; ++r)
    Sp[r] = reinterpret_cast<Smem*>(cl.map_shared_rank(&S, r));

  // Load own 32 rows of support; zero transposed hidden states.
  for (int i = tid; i < NP * Nn; i += NT)
    S.P[i] = support[rank * NP * Nn + i];
  for (int i = tid; i < Un * Nn; i += NT) {
    S.th0[i] = 0.f;
    S.th1[i] = 0.f;
  }

  const int tlast = seq_len[b] - 1;  // uniform across the cluster

  for (int t = 0; t <= tlast; ++t) {
    // stage current frame TRANSPOSED: tx[c][n] (swizzled)
    const float4 xv = reinterpret_cast<const float4*>(
        x_all + ((size_t)b * Tn + t) * (Nn * DINn))[tid];
    {
      const int n = tid >> 2;
      const int c0 = (tid & 3) * 4;
      const int k = tid & 3;  // key8(c0+j) for all j<4
      const int base = ((n >> 2) ^ k) * 4 + (n & 3);
      S.tx[(c0 + 0) * Nn + base] = xv.x;
      S.tx[(c0 + 1) * Nn + base] = xv.y;
      S.tx[(c0 + 2) * Nn + base] = xv.z;
      S.tx[(c0 + 3) * Nn + base] = xv.w;
    }
    cell<DINn>(cl, S, Sp, tid, rank, S.tx, S.th0, W0g, b0g, W0c, b0c);
    cell<Un>(cl, S, Sp, tid, rank, S.th0, S.th1, W1g, b1g, W1c, b1c);
  }

  cl.sync();  // all th1 scatters visible in rank 0's copy

  if (rank == 0) {
    // classifier: max_n( relu(h1[n]) @ Wfc + bfc ); t1 is dead, use as scratch
    const int n = tid >> 2;
    const int c = tid & 3;
    float a = 0.f;
#pragma unroll 8
    for (int u = 0; u < Un; ++u) {
      const float hv = S.th1[u * Nn + (((n >> 2) ^ key8(u)) << 2) + (n & 3)];
      a = fmaf(fmaxf(hv, 0.f), Wfc[u * Cn + c], a);
    }
    S.t1[n * Cn + c] = a + bfc[c];
    __syncthreads();
    if (tid < Cn) {
      float m = S.t1[tid];
      for (int n2 = 1; n2 < Nn; ++n2) m = fmaxf(m, S.t1[n2 * Cn + tid]);
      out[b * Cn + tid] = m;
    }
  }
}

extern "C" void kernel_launch(void* const* d_in, const int* in_sizes, int n_in,
                              void* d_out, int out_size) {
  const float* x   = (const float*)d_in[0];
  const int*   sl  = (const int*)d_in[1];
  const float* sup = (const float*)d_in[2];
  const float* W0g = (const float*)d_in[3];
  const float* b0g = (const float*)d_in[4];
  const float* W0c = (const float*)d_in[5];
  const float* b0c = (const float*)d_in[6];
  const float* W1g = (const float*)d_in[7];
  const float* b1g = (const float*)d_in[8];
  const float* W1c = (const float*)d_in[9];
  const float* b1c = (const float*)d_in[10];
  const float* Wfc = (const float*)d_in[11];
  const float* bfc = (const float*)d_in[12];
  float* out = (float*)d_out;

  const size_t smem = sizeof(Smem);
  cudaFuncSetAttribute(dcgru_kernel,
                       cudaFuncAttributeMaxDynamicSharedMemorySize, (int)smem);
  dcgru_kernel<<<Bn * CLS, NT, smem>>>(x, sl, sup, W0g, b0g, W0c, b0c,
                                       W1g, b1g, W1c, b1c, Wfc, bfc, out);
}

// round 11
// speedup vs baseline: 5.2960x; 1.1188x over previous
#include <cuda_runtime.h>
#include <cooperative_groups.h>
#include <math.h>

namespace cgx = cooperative_groups;
#define DEVINL __device__ __forceinline__

namespace {

constexpr int Bn   = 32;   // batch
constexpr int Tn   = 256;  // timesteps
constexpr int Nn   = 128;  // nodes
constexpr int DINn = 16;   // input features
constexpr int Un   = 64;   // hidden units
constexpr int Cn   = 4;    // classes
constexpr int CLS  = 4;    // cluster size (CTAs per batch)
constexpr int NP   = 32;   // nodes owned per CTA
constexpr int NT   = 512;  // threads per CTA

typedef unsigned long long ull;

// packed fp32x2 FMA (sm_103a): d.lo += a.lo*b.lo; d.hi += a.hi*b.hi (exact fp32)
DEVINL void fma2(ull& d, ull a, ull b) {
  asm("fma.rn.f32x2 %0, %1, %2, %0;" : "+l"(d) : "l"(a), "l"(b));
}
DEVINL ull dup2(float a) {
  ull r; asm("mov.b64 %0, {%1, %1};" : "=l"(r) : "f"(a)); return r;
}
DEVINL float2 lohi(ull v) {
  float2 r; asm("mov.b64 {%0, %1}, %2;" : "=f"(r.x), "=f"(r.y) : "l"(v)); return r;
}
DEVINL float rsum(ull v) { const float2 t = lohi(v); return t.x + t.y; }

// Activation buffers TRANSPOSED: t[c][n], 3-bit XOR swizzle on float4 granules.
struct Smem {
  float P[NP * Nn];     // own 32 rows of support           (16 KB)
  float P2[NP * Nn];    // own 32 rows of support^2         (16 KB)
  float tx[DINn * Nn];  // transposed input frame           ( 8 KB)
  float th0[Un * Nn];   // transposed hidden, layer 0       (32 KB)
  float th1[Un * Nn];   // transposed hidden, layer 1       (32 KB)
  float trh[Un * Nn];   // transposed r*h                   (32 KB)
  float t1[Nn * NP];    // P z,   own nodes [c][n local]    (16 KB)
  float t2[Nn * NP];    // 2P^2z - z, own [c][n local]      (16 KB)
  float ub[Un * NP];    // update gate [u][n local]         ( 8 KB)
};                      // 45056 floats = 180224 B

DEVINL int key8(int c) { return (c >> 2) & 7; }

// row base + swizzle key for concat channel c (x-part then h-part)
template <int CH0>
DEVINL const float* zrow(const float* __restrict__ s0t,
                         const float* __restrict__ s1t, int c, int& key) {
  if (c < CH0) { key = key8(c); return s0t + c * Nn; }
  const int ch = c - CH0;
  key = key8(ch);
  return s1t + ch * Nn;
}

// ---- gate hop1 (warps 0-7): t1[c][n] = sum_k P[n][k] z[k][c], LOCAL only.
template <int CH0>
DEVINL void hop1g(Smem& S, int t, const float* __restrict__ s0t,
                  const float* __restrict__ s1t) {
  constexpr int CIN = CH0 + Un;
  const int lane = t & 31;
  const int c4 = lane * 4;
  if (c4 >= CIN) return;
  const int n0 = (t >> 5) * 4;
  const float* Pr0 = &S.P[(n0 + 0) * Nn];
  const float* Pr1 = &S.P[(n0 + 1) * Nn];
  const float* Pr2 = &S.P[(n0 + 2) * Nn];
  const float* Pr3 = &S.P[(n0 + 3) * Nn];
  const float* zr[4];
  int zk[4];
#pragma unroll
  for (int j = 0; j < 4; ++j) zr[j] = zrow<CH0>(s0t, s1t, c4 + j, zk[j]);
  ull a2[4][4] = {};
#pragma unroll 2
  for (int k = 0; k < Nn; k += 4) {
    const int g = k >> 2;
    const ulonglong2 p0 = *reinterpret_cast<const ulonglong2*>(Pr0 + k);
    const ulonglong2 p1 = *reinterpret_cast<const ulonglong2*>(Pr1 + k);
    const ulonglong2 p2 = *reinterpret_cast<const ulonglong2*>(Pr2 + k);
    const ulonglong2 p3 = *reinterpret_cast<const ulonglong2*>(Pr3 + k);
#pragma unroll
    for (int j = 0; j < 4; ++j) {
      const ulonglong2 z = *reinterpret_cast<const ulonglong2*>(
          zr[j] + ((g ^ zk[j]) << 2));
      fma2(a2[0][j], p0.x, z.x); fma2(a2[0][j], p0.y, z.y);
      fma2(a2[1][j], p1.x, z.x); fma2(a2[1][j], p1.y, z.y);
      fma2(a2[2][j], p2.x, z.x); fma2(a2[2][j], p2.y, z.y);
      fma2(a2[3][j], p3.x, z.x); fma2(a2[3][j], p3.y, z.y);
    }
  }
  const int gl = n0 >> 2;
  const int tk = lane & 7;  // == key8(c4+j)
#pragma unroll
  for (int j = 0; j < 4; ++j)
    *reinterpret_cast<float4*>(&S.t1[(c4 + j) * NP + ((gl ^ tk) << 2)]) =
        make_float4(rsum(a2[0][j]), rsum(a2[1][j]),
                    rsum(a2[2][j]), rsum(a2[3][j]));
}

// ---- gate hop2 (warps 8-15): t2[c][n] = 2*sum_k P2[n][k] z[k][c] - z[n][c].
template <int CH0>
DEVINL void hop2g(Smem& S, int t, int rank, const float* __restrict__ s0t,
                  const float* __restrict__ s1t) {
  constexpr int CIN = CH0 + Un;
  const int lane = t & 31;
  const int c4 = lane * 4;
  if (c4 >= CIN) return;
  const int n0 = (t >> 5) * 4;
  const float* Pr0 = &S.P2[(n0 + 0) * Nn];
  const float* Pr1 = &S.P2[(n0 + 1) * Nn];
  const float* Pr2 = &S.P2[(n0 + 2) * Nn];
  const float* Pr3 = &S.P2[(n0 + 3) * Nn];
  const float* zr[4];
  int zk[4];
#pragma unroll
  for (int j = 0; j < 4; ++j) zr[j] = zrow<CH0>(s0t, s1t, c4 + j, zk[j]);
  ull a2[4][4] = {};
#pragma unroll 2
  for (int k = 0; k < Nn; k += 4) {
    const int g = k >> 2;
    const ulonglong2 p0 = *reinterpret_cast<const ulonglong2*>(Pr0 + k);
    const ulonglong2 p1 = *reinterpret_cast<const ulonglong2*>(Pr1 + k);
    const ulonglong2 p2 = *reinterpret_cast<const ulonglong2*>(Pr2 + k);
    const ulonglong2 p3 = *reinterpret_cast<const ulonglong2*>(Pr3 + k);
#pragma unroll
    for (int j = 0; j < 4; ++j) {
      const ulonglong2 z = *reinterpret_cast<const ulonglong2*>(
          zr[j] + ((g ^ zk[j]) << 2));
      fma2(a2[0][j], p0.x, z.x); fma2(a2[0][j], p0.y, z.y);
      fma2(a2[1][j], p1.x, z.x); fma2(a2[1][j], p1.y, z.y);
      fma2(a2[2][j], p2.x, z.x); fma2(a2[2][j], p2.y, z.y);
      fma2(a2[3][j], p3.x, z.x); fma2(a2[3][j], p3.y, z.y);
    }
  }
  const int gl = n0 >> 2;
  const int g0 = (rank * NP + n0) >> 2;
  const int tk = lane & 7;
#pragma unroll
  for (int j = 0; j < 4; ++j) {
    const float4 z0 = *reinterpret_cast<const float4*>(
        zr[j] + ((g0 ^ zk[j]) << 2));
    *reinterpret_cast<float4*>(&S.t2[(c4 + j) * NP + ((gl ^ tk) << 2)]) =
        make_float4(2.f * rsum(a2[0][j]) - z0.x, 2.f * rsum(a2[1][j]) - z0.y,
                    2.f * rsum(a2[2][j]) - z0.z, 2.f * rsum(a2[3][j]) - z0.w);
  }
}

// ---- candidate hop1 (warps 0-7): rh channels only -> t1 rows [CH0, CH0+64).
// thread = (node pair, 4 rh-channels); x-part rows persist from gate phase.
template <int CH0>
DEVINL void hop1cd(Smem& S, int t) {
  const int cn = t & 15;
  const int ch4 = cn * 4;
  const int tk = cn & 7;  // key8(ch4+j) in trh
  const int n0 = (t >> 4) * 2;
  const float* Pr0 = &S.P[(n0 + 0) * Nn];
  const float* Pr1 = &S.P[(n0 + 1) * Nn];
  const float* zr[4];
#pragma unroll
  for (int j = 0; j < 4; ++j) zr[j] = &S.trh[(ch4 + j) * Nn];
  ull a2[2][4] = {};
#pragma unroll 2
  for (int k = 0; k < Nn; k += 4) {
    const int g = (k >> 2) ^ tk;
    const ulonglong2 p0 = *reinterpret_cast<const ulonglong2*>(Pr0 + k);
    const ulonglong2 p1 = *reinterpret_cast<const ulonglong2*>(Pr1 + k);
#pragma unroll
    for (int j = 0; j < 4; ++j) {
      const ulonglong2 z = *reinterpret_cast<const ulonglong2*>(zr[j] + (g << 2));
      fma2(a2[0][j], p0.x, z.x); fma2(a2[0][j], p0.y, z.y);
      fma2(a2[1][j], p1.x, z.x); fma2(a2[1][j], p1.y, z.y);
    }
  }
  const int ksd = ((CH0 >> 2) + cn) & 7;  // key8 of destination row CH0+ch4+j
  const int gl = n0 >> 2, ofl = n0 & 3;
#pragma unroll
  for (int j = 0; j < 4; ++j)
    *reinterpret_cast<float2*>(
        &S.t1[(CH0 + ch4 + j) * NP + ((gl ^ ksd) << 2) + ofl]) =
        make_float2(rsum(a2[0][j]), rsum(a2[1][j]));
}

// ---- candidate hop2 (warps 8-15): rh channels via P2 -> t2 rows [CH0, CH0+64).
template <int CH0>
DEVINL void hop2cd(Smem& S, int t, int rank) {
  const int cn = t & 15;
  const int ch4 = cn * 4;
  const int tk = cn & 7;
  const int n0 = (t >> 4) * 2;
  const float* Pr0 = &S.P2[(n0 + 0) * Nn];
  const float* Pr1 = &S.P2[(n0 + 1) * Nn];
  const float* zr[4];
#pragma unroll
  for (int j = 0; j < 4; ++j) zr[j] = &S.trh[(ch4 + j) * Nn];
  ull a2[2][4] = {};
#pragma unroll 2
  for (int k = 0; k < Nn; k += 4) {
    const int g = (k >> 2) ^ tk;
    const ulonglong2 p0 = *reinterpret_cast<const ulonglong2*>(Pr0 + k);
    const ulonglong2 p1 = *reinterpret_cast<const ulonglong2*>(Pr1 + k);
#pragma unroll
    for (int j = 0; j < 4; ++j) {
      const ulonglong2 z = *reinterpret_cast<const ulonglong2*>(zr[j] + (g << 2));
      fma2(a2[0][j], p0.x, z.x); fma2(a2[0][j], p0.y, z.y);
      fma2(a2[1][j], p1.x, z.x); fma2(a2[1][j], p1.y, z.y);
    }
  }
  const int ksd = ((CH0 >> 2) + cn) & 7;
  const int ng0 = rank * NP + n0;
  const int gw = ng0 >> 2, ofs = ng0 & 3;
  const int gl = n0 >> 2, ofl = n0 & 3;
#pragma unroll
  for (int j = 0; j < 4; ++j) {
    const float2 z0 = *reinterpret_cast<const float2*>(
        &S.trh[(ch4 + j) * Nn + ((gw ^ tk) << 2) + ofs]);
    *reinterpret_cast<float2*>(
        &S.t2[(CH0 + ch4 + j) * NP + ((gl ^ ksd) << 2) + ofl]) =
        make_float2(2.f * rsum(a2[0][j]) - z0.x, 2.f * rsum(a2[1][j]) - z0.y);
  }
}

// ---- projection: acc2[q] packs node pairs; t1/t2 now local (stride NP).
template <int CH0, int COUT, int NPT>
DEVINL void accum(Smem& S, int tid, int rank, const float* __restrict__ W,
                  const float* __restrict__ s0t, const float* __restrict__ s1t,
                  ull* __restrict__ acc2) {
  constexpr int CIN = CH0 + Un;
  constexpr int LPO = NT / COUT;  // threads per output column
  const int oc = tid / LPO;
  const int n0 = (tid % LPO) * NPT;
  const int g1 = (rank * NP + n0) >> 2;  // global granule (replicated z0)
  const int g2 = n0 >> 2;                // local granule (t1, t2)
#pragma unroll 4
  for (int c = 0; c < CIN; ++c) {
    const ull w0 = dup2(W[(3 * c + 0) * COUT + oc]);
    const ull w1 = dup2(W[(3 * c + 1) * COUT + oc]);
    const ull w2 = dup2(W[(3 * c + 2) * COUT + oc]);
    const int k = key8(c);
    int zk;
    const float* zr = zrow<CH0>(s0t, s1t, c, zk);
    const float* t1r = &S.t1[c * NP];
    const float* t2r = &S.t2[c * NP];
#pragma unroll
    for (int q = 0; q < NPT / 4; ++q) {
      const ulonglong2 z0 = *reinterpret_cast<const ulonglong2*>(
          zr + (((g1 + q) ^ zk) << 2));
      const ulonglong2 z1 = *reinterpret_cast<const ulonglong2*>(
          t1r + (((g2 + q) ^ k) << 2));
      const ulonglong2 z2 = *reinterpret_cast<const ulonglong2*>(
          t2r + (((g2 + q) ^ k) << 2));
      fma2(acc2[2 * q + 0], z0.x, w0);
      fma2(acc2[2 * q + 0], z1.x, w1);
      fma2(acc2[2 * q + 0], z2.x, w2);
      fma2(acc2[2 * q + 1], z0.y, w0);
      fma2(acc2[2 * q + 1], z1.y, w1);
      fma2(acc2[2 * q + 1], z2.y, w2);
    }
  }
}

// ---- one DCGRU cell, cluster-cooperative; ht = this layer's transposed h.
template <int CH0>
DEVINL void cell(cgx::cluster_group& cl, Smem& S, Smem* const* Sp, int tid,
                 int rank, const float* __restrict__ s0t, float* __restrict__ ht,
                 const float* __restrict__ Wg, const float* __restrict__ bg,
                 const float* __restrict__ Wc, const float* __restrict__ bc) {
  const size_t hoff = (size_t)((const char*)ht - (const char*)&S);

  // ================= gate =================
  cl.sync();  // replicated inputs (h / trh / h-scatters) visible everywhere
  if (tid < 256) hop1g<CH0>(S, tid, s0t, ht);
  else           hop2g<CH0>(S, tid - 256, rank, s0t, ht);
  __syncthreads();
  {
    ull acc2[4] = {0ull, 0ull, 0ull, 0ull};
    accum<CH0, 128, 8>(S, tid, rank, Wg, s0t, ht, acc2);
    float acc[8];
#pragma unroll
    for (int q = 0; q < 4; ++q) {
      const float2 t = lohi(acc2[q]);
      acc[2 * q] = t.x;
      acc[2 * q + 1] = t.y;
    }
    const int oc = tid >> 2;
    const int n0 = (tid & 3) * 8;
    const int ng0 = rank * NP + n0;
    const float bias = bg[oc];
    float v[8];
#pragma unroll
    for (int i = 0; i < 8; ++i)
      v[i] = 1.f / (1.f + __expf(-(acc[i] + bias)));
    if (oc < Un) {  // r-part -> trh (transposed), scattered to all ranks
      const int k = key8(oc);
      const int g = ng0 >> 2;
      const float* hr = ht + oc * Nn;
      const float4 h0 = *reinterpret_cast<const float4*>(hr + ((g ^ k) << 2));
      const float4 h1 = *reinterpret_cast<const float4*>(hr + (((g + 1) ^ k) << 2));
      const float4 r0 = make_float4(v[0] * h0.x, v[1] * h0.y, v[2] * h0.z, v[3] * h0.w);
      const float4 r1 = make_float4(v[4] * h1.x, v[5] * h1.y, v[6] * h1.z, v[7] * h1.w);
#pragma unroll
      for (int r = 0; r < CLS; ++r) {
        float* base = &Sp[r]->trh[oc * Nn];
        *reinterpret_cast<float4*>(base + ((g ^ k) << 2)) = r0;
        *reinterpret_cast<float4*>(base + (((g + 1) ^ k) << 2)) = r1;
      }
    } else {  // u-part -> local ub (transposed)
      const int ou = oc - Un;
      const int ku = key8(ou);
      const int gl = n0 >> 2;
      float* ur = &S.ub[ou * NP];
      *reinterpret_cast<float4*>(ur + ((gl ^ ku) << 2)) =
          make_float4(v[0], v[1], v[2], v[3]);
      *reinterpret_cast<float4*>(ur + (((gl + 1) ^ ku) << 2)) =
          make_float4(v[4], v[5], v[6], v[7]);
    }
  }

  // ================= candidate + update =================
  cl.sync();  // trh gathered everywhere; all ranks past gate accum
  if (tid < 256) hop1cd<CH0>(S, tid);
  else           hop2cd<CH0>(S, tid - 256, rank);
  __syncthreads();
  {
    ull acc2[2] = {0ull, 0ull};
    accum<CH0, 64, 4>(S, tid, rank, Wc, s0t, S.trh, acc2);
    float acc[4];
    {
      float2 t = lohi(acc2[0]);
      acc[0] = t.x; acc[1] = t.y;
      t = lohi(acc2[1]);
      acc[2] = t.x; acc[3] = t.y;
    }
    const int oc = tid >> 3;
    const int n0 = (tid & 7) * 4;
    const int ng0 = rank * NP + n0;
    const int k = key8(oc);
    const float bias = bc[oc];
    const float4 uu = *reinterpret_cast<const float4*>(
        &S.ub[oc * NP] + (((n0 >> 2) ^ k) << 2));
    const int go = ((ng0 >> 2) ^ k) << 2;
    const float4 hh = *reinterpret_cast<const float4*>(ht + oc * Nn + go);
    float4 hn;
    hn.x = uu.x * hh.x + (1.f - uu.x) * tanhf(acc[0] + bias);
    hn.y = uu.y * hh.y + (1.f - uu.y) * tanhf(acc[1] + bias);
    hn.z = uu.z * hh.z + (1.f - uu.z) * tanhf(acc[2] + bias);
    hn.w = uu.w * hh.w + (1.f - uu.w) * tanhf(acc[3] + bias);
#pragma unroll
    for (int r = 0; r < CLS; ++r) {
      float* hp = reinterpret_cast<float*>((char*)Sp[r] + hoff);
      *reinterpret_cast<float4*>(hp + oc * Nn + go) = hn;
    }
  }
}

}  // namespace

__global__ void __launch_bounds__(NT, 1) __cluster_dims__(CLS, 1, 1)
dcgru_kernel(
    const float* __restrict__ x_all,   // (B,T,N,DIN)
    const int* __restrict__ seq_len,   // (B)
    const float* __restrict__ support, // (N,N)
    const float* __restrict__ W0g, const float* __restrict__ b0g,
    const float* __restrict__ W0c, const float* __restrict__ b0c,
    const float* __restrict__ W1g, const float* __restrict__ b1g,
    const float* __restrict__ W1c, const float* __restrict__ b1c,
    const float* __restrict__ Wfc, const float* __restrict__ bfc,
    float* __restrict__ out) {         // (B,C)
  extern __shared__ float smraw[];
  Smem& S = *reinterpret_cast<Smem*>(smraw);
  cgx::cluster_group cl = cgx::this_cluster();
  const int rank = cl.block_rank();
  const int b = blockIdx.x / CLS;
  const int tid = threadIdx.x;

  Smem* Sp[CLS];
#pragma unroll
  for (int r = 0; r < CLS; ++r)
    Sp[r] = reinterpret_cast<Smem*>(cl.map_shared_rank(&S, r));

  // Load own 32 rows of support.
  for (int i = tid; i < NP * Nn; i += NT)
    S.P[i] = support[rank * NP * Nn + i];
  __syncthreads();

  // Precompute P2 = (own rows of) support^2. thread = (node, 8 k-values).
  {
    const int n = tid >> 4;
    const int k8 = (tid & 15) * 8;
    const float* Pr = &S.P[n * Nn];
    float acc[8] = {0.f, 0.f, 0.f, 0.f, 0.f, 0.f, 0.f, 0.f};
    for (int m = 0; m < Nn; ++m) {
      const float p = Pr[m];
      const float4 sa = *reinterpret_cast<const float4*>(
          support + (size_t)m * Nn + k8);
      const float4 sb = *reinterpret_cast<const float4*>(
          support + (size_t)m * Nn + k8 + 4);
      acc[0] = fmaf(p, sa.x, acc[0]); acc[1] = fmaf(p, sa.y, acc[1]);
      acc[2] = fmaf(p, sa.z, acc[2]); acc[3] = fmaf(p, sa.w, acc[3]);
      acc[4] = fmaf(p, sb.x, acc[4]); acc[5] = fmaf(p, sb.y, acc[5]);
      acc[6] = fmaf(p, sb.z, acc[6]); acc[7] = fmaf(p, sb.w, acc[7]);
    }
#pragma unroll
    for (int j = 0; j < 8; ++j) S.P2[n * Nn + k8 + j] = acc[j];
  }

  // Zero transposed hidden states.
  for (int i = tid; i < Un * Nn; i += NT) {
    S.th0[i] = 0.f;
    S.th1[i] = 0.f;
  }

  const int tlast = seq_len[b] - 1;  // uniform across the cluster

  for (int t = 0; t <= tlast; ++t) {
    // stage current frame TRANSPOSED: tx[c][n] (swizzled)
    const float4 xv = reinterpret_cast<const float4*>(
        x_all + ((size_t)b * Tn + t) * (Nn * DINn))[tid];
    {
      const int n = tid >> 2;
      const int c0 = (tid & 3) * 4;
      const int k = tid & 3;  // key8(c0+j) for all j<4
      const int base = ((n >> 2) ^ k) * 4 + (n & 3);
      S.tx[(c0 + 0) * Nn + base] = xv.x;
      S.tx[(c0 + 1) * Nn + base] = xv.y;
      S.tx[(c0 + 2) * Nn + base] = xv.z;
      S.tx[(c0 + 3) * Nn + base] = xv.w;
    }
    cell<DINn>(cl, S, Sp, tid, rank, S.tx, S.th0, W0g, b0g, W0c, b0c);
    cell<Un>(cl, S, Sp, tid, rank, S.th0, S.th1, W1g, b1g, W1c, b1c);
  }

  cl.sync();  // all th1 scatters visible in rank 0's copy

  if (rank == 0) {
    // classifier: max_n( relu(h1[n]) @ Wfc + bfc ); t1 is dead, use as scratch
    const int n = tid >> 2;
    const int c = tid & 3;
    float a = 0.f;
#pragma unroll 8
    for (int u = 0; u < Un; ++u) {
      const float hv = S.th1[u * Nn + (((n >> 2) ^ key8(u)) << 2) + (n & 3)];
      a = fmaf(fmaxf(hv, 0.f), Wfc[u * Cn + c], a);
    }
    S.t1[n * Cn + c] = a + bfc[c];
    __syncthreads();
    if (tid < Cn) {
      float m = S.t1[tid];
      for (int n2 = 1; n2 < Nn; ++n2) m = fmaxf(m, S.t1[n2 * Cn + tid]);
      out[b * Cn + tid] = m;
    }
  }
}

extern "C" void kernel_launch(void* const* d_in, const int* in_sizes, int n_in,
                              void* d_out, int out_size) {
  const float* x   = (const float*)d_in[0];
  const int*   sl  = (const int*)d_in[1];
  const float* sup = (const float*)d_in[2];
  const float* W0g = (const float*)d_in[3];
  const float* b0g = (const float*)d_in[4];
  const float* W0c = (const float*)d_in[5];
  const float* b0c = (const float*)d_in[6];
  const float* W1g = (const float*)d_in[7];
  const float* b1g = (const float*)d_in[8];
  const float* W1c = (const float*)d_in[9];
  const float* b1c = (const float*)d_in[10];
  const float* Wfc = (const float*)d_in[11];
  const float* bfc = (const float*)d_in[12];
  float* out = (float*)d_out;

  const size_t smem = sizeof(Smem);
  cudaFuncSetAttribute(dcgru_kernel,
                       cudaFuncAttributeMaxDynamicSharedMemorySize, (int)smem);
  dcgru_kernel<<<Bn * CLS, NT, smem>>>(x, sl, sup, W0g, b0g, W0c, b0c,
                                       W1g, b1g, W1c, b1c, Wfc, bfc, out);
}